// round 14
// baseline (speedup 1.0000x reference)
#include <cuda_runtime.h>
#include <cuda_bf16.h>
#include <math.h>
#include <stdint.h>

#define LAYERS 30
#define B_SZ 4
#define TLEN 32000
#define TT 64
#define NTILES (B_SZ * (TLEN / TT))
#define LTT 64
#define LNT (B_SZ * (TLEN / LTT))   /* 2000 */
#define CH 64
#define CCH 80

/* layer SMEM: double B1, double B2, epilogue staging */
#define STR 144
#define SM_BUF 59904              /* one B1 buffer: hi 29952 + mid 29952 */
#define SM_B1M_OFF 29952
#define SM_B2 119808              /* + q*18432 ; mid at +9216 */
#define SM_EPI_SK 156672          /* skips fp32 [64] rows of 272B */
#define SM_EPI_HH 174080          /* h hi  [64] rows of 144B */
#define SM_EPI_HM 183296          /* h mid [64] rows of 144B */
#define SM_TOTAL 192512

typedef unsigned long long u64;
typedef uint32_t u32;
typedef unsigned short u16;

__device__ __nv_bfloat16 g_hh[2][B_SZ * CH * TLEN];
__device__ __nv_bfloat16 g_hm[2][B_SZ * CH * TLEN];
__device__ float g_skips[B_SZ * CH * TLEN];
__device__ __nv_bfloat16 g_cbh[B_SZ * CCH * TLEN];
__device__ __nv_bfloat16 g_cbm[B_SZ * CCH * TLEN];
__device__ u32 g_gwh[LAYERS * 128 * 104];
__device__ u32 g_gwm[LAYERS * 128 * 104];
__device__ u32 g_wzh[LAYERS * 128 * 32];
__device__ u32 g_wzm[LAYERS * 128 * 32];
__device__ float g_wfirstT[256 * 64];
__device__ float g_wl1T[64 * 64];
__device__ float g_wl2T[64 * 256];

__device__ __forceinline__ u32 pkbf(float a, float b) {
    __nv_bfloat162 h = __floats2bfloat162_rn(a, b);
    return *reinterpret_cast<u32*>(&h);
}
__device__ __forceinline__ float bflo(float a) { return __bfloat162float(__float2bfloat16(a)); }
__device__ __forceinline__ float2 upbf(u32 v) {
    __nv_bfloat162 h = *reinterpret_cast<__nv_bfloat162*>(&v);
    return make_float2(__bfloat162float(h.x), __bfloat162float(h.y));
}
__device__ __forceinline__ float gact(float a, float b) {
    a = fmaxf(a, -15.f);
    b = fmaxf(b, -30.f);
    float e1 = __expf(-2.f * a);
    float e2 = __expf(-b);
    return (1.f - e1) * __fdividef(1.f, (1.f + e1) * (1.f + e2));
}

__device__ __forceinline__ u32 smem_u32(const void* p) {
    u32 a;
    asm("{ .reg .u64 t; cvta.to.shared.u64 t, %1; cvt.u32.u64 %0, t; }" : "=r"(a) : "l"(p));
    return a;
}
__device__ __forceinline__ void mma16816(float* d, const u32* a, const u32* b) {
    asm volatile("mma.sync.aligned.m16n8k16.row.col.f32.bf16.bf16.f32 "
        "{%0,%1,%2,%3}, {%4,%5,%6,%7}, {%8,%9}, {%0,%1,%2,%3};"
        : "+f"(d[0]), "+f"(d[1]), "+f"(d[2]), "+f"(d[3])
        : "r"(a[0]), "r"(a[1]), "r"(a[2]), "r"(a[3]), "r"(b[0]), "r"(b[1]));
}
__device__ __forceinline__ void ldmT_x4(u32* r, u32 addr) {
    asm volatile("ldmatrix.sync.aligned.m8n8.x4.trans.shared.b16 {%0,%1,%2,%3}, [%4];"
        : "=r"(r[0]), "=r"(r[1]), "=r"(r[2]), "=r"(r[3]) : "r"(addr));
}
__device__ __forceinline__ void ldmT_x2(u32* r, u32 addr) {
    asm volatile("ldmatrix.sync.aligned.m8n8.x2.trans.shared.b16 {%0,%1}, [%2];"
        : "=r"(r[0]), "=r"(r[1]) : "r"(addr));
}
#define CP16(dst, src) asm volatile("cp.async.cg.shared.global [%0], [%1], 16;" \
    :: "r"((u32)(dst)), "l"(src) : "memory")
#define CP8(dst, src)  asm volatile("cp.async.ca.shared.global [%0], [%1], 8;" \
    :: "r"((u32)(dst)), "l"(src) : "memory")
#define CP4(dst, src)  asm volatile("cp.async.ca.shared.global [%0], [%1], 4;" \
    :: "r"((u32)(dst)), "l"(src) : "memory")
#define CP_COMMIT() asm volatile("cp.async.commit_group;" ::: "memory")
#define CP_WAIT0()  asm volatile("cp.async.wait_group 0;" ::: "memory")
#define STS32(a, v) asm volatile("st.shared.b32 [%0], %1;" :: "r"((u32)(a)), "r"((u32)(v)) : "memory")

__device__ __forceinline__ u64 pk2(float lo, float hi) {
    u64 r; asm("mov.b64 %0, {%1, %2};" : "=l"(r) : "f"(lo), "f"(hi)); return r;
}
__device__ __forceinline__ u64 dup2f(float v) { return pk2(v, v); }
__device__ __forceinline__ void fma2(u64& d, u64 a, u64 b) {
    asm("fma.rn.f32x2 %0, %1, %2, %0;" : "+l"(d) : "l"(a), "l"(b));
}
__device__ __forceinline__ void upk(float& lo, float& hi, u64 v) {
    asm("mov.b64 {%0, %1}, %2;" : "=f"(lo), "=f"(hi) : "l"(v));
}

__device__ __forceinline__ int orig_gate_row(int r) {
    int q = r >> 4, i = r & 15;
    return (i < 8) ? (8 * q + i) : (64 + 8 * q + (i - 8));
}

/* ---------------- merged weight prep ---------------- */
#define NPG (LAYERS * 128 * 104)
#define NPZ (LAYERS * 128 * 32)
#define NPF (16384 + 4096 + 16384)
__global__ void prep_all_kernel(const float* __restrict__ conv_w,
                                const float* __restrict__ cond_w,
                                const float* __restrict__ skip_w,
                                const float* __restrict__ out_w,
                                const float* __restrict__ first_w,
                                const float* __restrict__ last1_w,
                                const float* __restrict__ last2_w) {
    int idx = blockIdx.x * blockDim.x + threadIdx.x;
    if (idx < NPG) {
        int l = idx / (128 * 104), rem = idx % (128 * 104);
        int r = rem / 104, kp = rem % 104;
        int o = orig_gate_row(r);
        float w[2];
#pragma unroll
        for (int e = 0; e < 2; ++e) {
            int k = 2 * kp + e;
            if (k < 64)       w[e] = conv_w[((l * 128 + o) * 64 + k) * 2 + 0];
            else if (k < 128) w[e] = conv_w[((l * 128 + o) * 64 + (k - 64)) * 2 + 1];
            else              w[e] = cond_w[(l * 128 + o) * 80 + (k - 128)];
        }
        g_gwh[idx] = pkbf(w[0], w[1]);
        g_gwm[idx] = pkbf(w[0] - bflo(w[0]), w[1] - bflo(w[1]));
    } else if (idx < NPG + NPZ) {
        int j = idx - NPG;
        int l = j / (128 * 32), rem = j % (128 * 32);
        int r = rem / 32, kp = rem % 32;
        float w[2];
#pragma unroll
        for (int e = 0; e < 2; ++e) {
            int k = 2 * kp + e;
            w[e] = (r < 64) ? skip_w[(l * 64 + r) * 64 + k]
                            : out_w[(l * 64 + (r - 64)) * 64 + k];
        }
        g_wzh[j] = pkbf(w[0], w[1]);
        g_wzm[j] = pkbf(w[0] - bflo(w[0]), w[1] - bflo(w[1]));
    } else if (idx < NPG + NPZ + NPF) {
        int j = idx - NPG - NPZ;
        if (j < 16384) {
            int c = j >> 6, o = j & 63;
            g_wfirstT[j] = first_w[o * 256 + c];
        } else if (j < 16384 + 4096) {
            int jj = j - 16384; int c = jj >> 6, o = jj & 63;
            g_wl1T[jj] = last1_w[o * 64 + c];
        } else {
            int jj = j - 16384 - 4096; int c = jj >> 8, o = jj & 255;
            g_wl2T[jj] = last2_w[o * 64 + c];
        }
    }
}

/* ---------------- merged conditioning ---------------- */
__global__ void __launch_bounds__(256) cond_all_kernel(
        const float* __restrict__ cin, const float* __restrict__ conv_in_w,
        const float* __restrict__ w0, const float* __restrict__ w1) {
    __shared__ float c1row[400];
    __shared__ float c2row[4000];
    int blk = blockIdx.x;
    int b = blk / CCH, o = blk % CCH;
    int tid = threadIdx.x;
    for (int f = tid; f < 400; f += 256) {
        const float* src = cin + (size_t)(b * CCH) * 400 + f;
        float acc = 0.f;
#pragma unroll 8
        for (int ch = 0; ch < 80; ++ch)
            acc += __ldg(&conv_in_w[o * 80 + ch]) * __ldg(&src[ch * 400]);
        c1row[f] = acc;
    }
    __syncthreads();
    for (int t = tid; t < 4000; t += 256) {
        float acc = 0.f;
        int base = t - 10;
        for (int j = 0; j < 21; ++j) {
            int u = base + j;
            if (u >= 0 && u < 4000) acc += __ldg(&w0[j]) * c1row[u / 10];
        }
        c2row[t] = acc;
    }
    __syncthreads();
    size_t rowoff = (size_t)(b * CCH + o) * TLEN;
    for (int t = tid; t < TLEN; t += 256) {
        float acc = 0.f;
        int base = t - 8;
        for (int j = 0; j < 17; ++j) {
            int u = base + j;
            if (u >= 0 && u < TLEN) acc += __ldg(&w1[j]) * c2row[u / 8];
        }
        g_cbh[rowoff + t] = __float2bfloat16(acc);
        g_cbm[rowoff + t] = __float2bfloat16(acc - bflo(acc));
    }
}

/* ---------------- first 1x1 conv (FFMA2) -> bf16 hi/mid planes ------------- */
__global__ void __launch_bounds__(256) first_kernel(const float* __restrict__ x,
                                                    const float* __restrict__ first_b) {
    extern __shared__ float sm[];
    float* xs = sm;
    float* wf = sm + 16384;
    for (int i = threadIdx.x; i < 16384 / 4; i += blockDim.x)
        ((float4*)wf)[i] = ((const float4*)g_wfirstT)[i];
    int to = threadIdx.x & 15, oo = threadIdx.x >> 4;
    int tb = to * 4, ob = oo * 4;
    for (int tile = blockIdx.x; tile < NTILES; tile += gridDim.x) {
        int b = tile / (TLEN / TT), t0 = (tile % (TLEN / TT)) * TT;
        __syncthreads();
        const float* xb = x + (size_t)b * 256 * TLEN;
        for (int i = threadIdx.x; i < 256 * (TT / 4); i += blockDim.x) {
            int c = i / (TT / 4), q = i % (TT / 4);
            ((float4*)xs)[c * (TT / 4) + q] = *(const float4*)&xb[c * TLEN + t0 + q * 4];
        }
        __syncthreads();
        u64 acc[2][4];
#pragma unroll
        for (int op = 0; op < 2; ++op) {
            u64 bv = pk2(first_b[ob + 2 * op], first_b[ob + 2 * op + 1]);
#pragma unroll
            for (int ti = 0; ti < 4; ++ti) acc[op][ti] = bv;
        }
#pragma unroll 2
        for (int c = 0; c < 256; ++c) {
            float4 xv4 = *(const float4*)(xs + c * TT + tb);
            u64 xv[4] = {dup2f(xv4.x), dup2f(xv4.y), dup2f(xv4.z), dup2f(xv4.w)};
            ulonglong2 wv = *(const ulonglong2*)(wf + c * 64 + ob);
            u64 w2[2] = {wv.x, wv.y};
#pragma unroll
            for (int op = 0; op < 2; ++op)
#pragma unroll
                for (int ti = 0; ti < 4; ++ti) fma2(acc[op][ti], w2[op], xv[ti]);
        }
        __nv_bfloat16* hh = g_hh[0] + (size_t)b * CH * TLEN;
        __nv_bfloat16* hm = g_hm[0] + (size_t)b * CH * TLEN;
#pragma unroll
        for (int op = 0; op < 2; ++op) {
            float lo[4], hi[4];
#pragma unroll
            for (int ti = 0; ti < 4; ++ti) upk(lo[ti], hi[ti], acc[op][ti]);
            int r0 = ob + 2 * op, r1 = r0 + 1;
            u32* p;
            p = (u32*)(hh + (size_t)r0 * TLEN + t0 + tb);
            p[0] = pkbf(lo[0], lo[1]); p[1] = pkbf(lo[2], lo[3]);
            p = (u32*)(hm + (size_t)r0 * TLEN + t0 + tb);
            p[0] = pkbf(lo[0] - bflo(lo[0]), lo[1] - bflo(lo[1]));
            p[1] = pkbf(lo[2] - bflo(lo[2]), lo[3] - bflo(lo[3]));
            p = (u32*)(hh + (size_t)r1 * TLEN + t0 + tb);
            p[0] = pkbf(hi[0], hi[1]); p[1] = pkbf(hi[2], hi[3]);
            p = (u32*)(hm + (size_t)r1 * TLEN + t0 + tb);
            p[0] = pkbf(hi[0] - bflo(hi[0]), hi[1] - bflo(hi[1]));
            p[1] = pkbf(hi[2] - bflo(hi[2]), hi[3] - bflo(hi[3]));
        }
    }
}

/* ---- async B1 issue ---- */
__device__ __forceinline__ void issue_b1(char* smc, u32 sb, u32 bufoff, int tile,
                                         int d, const __nv_bfloat16* phh,
                                         const __nv_bfloat16* phm, int tid) {
    int b = tile / (TLEN / LTT), t0 = (tile % (TLEN / LTT)) * LTT;
    const __nv_bfloat16* hbh = phh + (size_t)b * CH * TLEN;
    const __nv_bfloat16* hbm = phm + (size_t)b * CH * TLEN;
    u32 dsth = sb + bufoff;
    u32 dstm = dsth + SM_B1M_OFF;
    for (int i = tid; i < 144 * 8; i += 256) {
        int r = i >> 3, g = i & 7;
        const __nv_bfloat16 *s1, *s2;
        if (r < 64) {
            size_t a = (size_t)r * TLEN + t0 + g * 8;
            s1 = hbh + a; s2 = hbm + a;
        } else {
            size_t a = ((size_t)(b * CCH + r - 64)) * TLEN + t0 + g * 8;
            s1 = g_cbh + a; s2 = g_cbm + a;
        }
        u32 off = (u32)((64 + r) * STR + g * 16);
        CP16(dsth + off, s1);
        CP16(dstm + off, s2);
    }
    for (int i = tid; i < 64 * 8; i += 256) {
        int r = i >> 3, g = i & 7;
        int tg = t0 - d + g * 8;
        const __nv_bfloat16* sh = hbh + (size_t)r * TLEN;
        const __nv_bfloat16* sm2 = hbm + (size_t)r * TLEN;
        u32 off = (u32)(r * STR + g * 16);
        if (tg >= 0 && d >= 8) {
            CP16(dsth + off, sh + tg);
            CP16(dstm + off, sm2 + tg);
        } else if (tg >= 0 && d == 4) {
            CP8(dsth + off, sh + tg);      CP8(dsth + off + 8, sh + tg + 4);
            CP8(dstm + off, sm2 + tg);     CP8(dstm + off + 8, sm2 + tg + 4);
        } else if (tg >= 0 && d == 2) {
#pragma unroll
            for (int q = 0; q < 4; ++q) {
                CP4(dsth + off + q * 4, sh + tg + q * 2);
                CP4(dstm + off + q * 4, sm2 + tg + q * 2);
            }
        } else {
#pragma unroll
            for (int e = 0; e < 4; ++e) {
                int tt0 = tg + 2 * e, tt1 = tt0 + 1;
                u16 h0 = (tt0 >= 0) ? *(const u16*)(sh + tt0) : 0;
                u16 h1 = (tt1 >= 0) ? *(const u16*)(sh + tt1) : 0;
                u16 m0 = (tt0 >= 0) ? *(const u16*)(sm2 + tt0) : 0;
                u16 m1 = (tt1 >= 0) ? *(const u16*)(sm2 + tt1) : 0;
                STS32(dsth + off + e * 4, (u32)h0 | ((u32)h1 << 16));
                STS32(dstm + off + e * 4, (u32)m0 | ((u32)m1 << 16));
            }
        }
    }
}

/* ---- async epilogue staging ---- */
__device__ __forceinline__ void issue_epi(u32 sb, int tile,
                                          const __nv_bfloat16* phh,
                                          const __nv_bfloat16* phm, int tid) {
    int b = tile / (TLEN / LTT), t0 = (tile % (TLEN / LTT)) * LTT;
    const float* skb = g_skips + (size_t)b * CH * TLEN;
    const __nv_bfloat16* hbh = phh + (size_t)b * CH * TLEN;
    const __nv_bfloat16* hbm = phm + (size_t)b * CH * TLEN;
    for (int i = tid; i < 1024; i += 256) {
        int r = i >> 4, g = i & 15;
        CP16(sb + SM_EPI_SK + r * 272 + g * 16, skb + (size_t)r * TLEN + t0 + g * 4);
    }
    for (int i = tid; i < 512; i += 256) {
        int r = i >> 3, g = i & 7;
        CP16(sb + SM_EPI_HH + r * 144 + g * 16, hbh + (size_t)r * TLEN + t0 + g * 8);
        CP16(sb + SM_EPI_HM + r * 144 + g * 16, hbm + (size_t)r * TLEN + t0 + g * 8);
    }
}

/* ---------------- fused residual layer: cross-tile pipelined --------------- */
__global__ void __launch_bounds__(256, 1) layer_kernel(int l, int d, int hin, int first_layer,
        const float* __restrict__ conv_b, const float* __restrict__ skip_b,
        const float* __restrict__ out_b) {
    extern __shared__ char smc[];
    u32 sb = smem_u32(smc);
    int tid = threadIdx.x, w = tid >> 5, lane = tid & 31;
    int lq = lane >> 2, lr = lane & 3;

    u32 Ah[13][4], Am[13][4], Zh[4][4], Zm[4][4];
    {
        const u32* gh = g_gwh + ((size_t)l * 128 + 16 * w) * 104;
        const u32* gm = g_gwm + ((size_t)l * 128 + 16 * w) * 104;
#pragma unroll
        for (int ks = 0; ks < 13; ++ks) {
            int kp = 8 * ks + lr;
            Ah[ks][0] = gh[lq * 104 + kp];     Ah[ks][1] = gh[(8 + lq) * 104 + kp];
            Ah[ks][2] = gh[lq * 104 + kp + 4]; Ah[ks][3] = gh[(8 + lq) * 104 + kp + 4];
            Am[ks][0] = gm[lq * 104 + kp];     Am[ks][1] = gm[(8 + lq) * 104 + kp];
            Am[ks][2] = gm[lq * 104 + kp + 4]; Am[ks][3] = gm[(8 + lq) * 104 + kp + 4];
        }
        const u32* zh = g_wzh + ((size_t)l * 128 + 16 * w) * 32;
        const u32* zm = g_wzm + ((size_t)l * 128 + 16 * w) * 32;
#pragma unroll
        for (int ks = 0; ks < 4; ++ks) {
            int kp = 8 * ks + lr;
            Zh[ks][0] = zh[lq * 32 + kp];     Zh[ks][1] = zh[(8 + lq) * 32 + kp];
            Zh[ks][2] = zh[lq * 32 + kp + 4]; Zh[ks][3] = zh[(8 + lq) * 32 + kp + 4];
            Zm[ks][0] = zm[lq * 32 + kp];     Zm[ks][1] = zm[(8 + lq) * 32 + kp];
            Zm[ks][2] = zm[lq * 32 + kp + 4]; Zm[ks][3] = zm[(8 + lq) * 32 + kp + 4];
        }
    }
    int gch = 8 * w + lq;
    float ba = conv_b[l * 128 + gch];
    float bb = conv_b[l * 128 + 64 + gch];
    int r1 = 16 * w + lq;
    float bs0 = (r1 < 64) ? skip_b[l * 64 + r1] : out_b[l * 64 + r1 - 64];
    float bs1 = (r1 < 64) ? skip_b[l * 64 + r1 + 8] : out_b[l * 64 + r1 - 56];

    const __nv_bfloat16* phh = g_hh[hin];
    const __nv_bfloat16* phm = g_hm[hin];
    __nv_bfloat16* qhh = g_hh[hin ^ 1];
    __nv_bfloat16* qhm = g_hm[hin ^ 1];

    int tile = blockIdx.x;
    if (tile >= LNT) return;

    /* prologue: B1(T0) */
    issue_b1(smc, sb, 0, tile, d, phh, phm, tid);
    CP_COMMIT();
    CP_WAIT0();
    __syncthreads();

    int nt = tile + gridDim.x;
    if (nt < LNT)
        issue_b1(smc, sb, SM_BUF, nt, d, phh, phm, tid);
    CP_COMMIT();

    /* ---- peel: gate(T0) from buf0 -> B2[0] ---- */
    {
        u32 bufH = sb;
        u32 bufM = bufH + SM_B1M_OFF;
        u32 b1h_l4 = bufH + lane * STR;
        u32 b1m_l4 = bufM + lane * STR;
        u32 b1h_l2 = bufH + (lane & 15) * STR + 192 * STR;
        u32 b1m_l2 = bufM + (lane & 15) * STR + 192 * STR;
        int wb2h_off = SM_B2, wb2m_off = SM_B2 + 9216;
#pragma unroll 1
        for (int j = 0; j < 8; ++j) {
            float D0[4] = {0, 0, 0, 0}, D1[4] = {0, 0, 0, 0}, D2[4] = {0, 0, 0, 0};
            int ta = j * 16;
#pragma unroll
            for (int kk = 0; kk < 6; ++kk) {
                u32 bh[4], bm[4];
                ldmT_x4(bh, b1h_l4 + kk * 32 * STR + ta);
                ldmT_x4(bm, b1m_l4 + kk * 32 * STR + ta);
                mma16816(D0, Ah[2 * kk], bh);
                mma16816(D1, Ah[2 * kk], bm);
                mma16816(D2, Am[2 * kk], bh);
                mma16816(D0, Ah[2 * kk + 1], bh + 2);
                mma16816(D1, Ah[2 * kk + 1], bm + 2);
                mma16816(D2, Am[2 * kk + 1], bh + 2);
            }
            {
                u32 bh[2], bm[2];
                ldmT_x2(bh, b1h_l2 + ta);
                ldmT_x2(bm, b1m_l2 + ta);
                mma16816(D0, Ah[12], bh);
                mma16816(D1, Ah[12], bm);
                mma16816(D2, Am[12], bh);
            }
            float a0 = D0[0] + D1[0] + D2[0] + ba;
            float a1 = D0[1] + D1[1] + D2[1] + ba;
            float g0 = D0[2] + D1[2] + D2[2] + bb;
            float g1 = D0[3] + D1[3] + D2[3] + bb;
            float z0 = gact(a0, g0), z1 = gact(a1, g1);
            int zoff = gch * STR + (j * 8 + lr * 2) * 2;
            *(u32*)(smc + wb2h_off + zoff) = pkbf(z0, z1);
            *(u32*)(smc + wb2m_off + zoff) = pkbf(z0 - bflo(z0), z1 - bflo(z1));
        }
    }
    issue_epi(sb, tile, phh, phm, tid);
    CP_COMMIT();

    int gbuf = 1, zb = 0;

    /* ---- combined loop: skip(tile) + gate(nt) ---- */
    while (nt < LNT) {
        CP_WAIT0();
        __syncthreads();   /* epi(tile)+B1(nt) landed; B2[zb] visible; bufs free */

        int nnt = nt + gridDim.x;
        if (nnt < LNT)
            issue_b1(smc, sb, (u32)((gbuf ^ 1) * SM_BUF), nnt, d, phh, phm, tid);
        CP_COMMIT();

        int b_s = tile / (TLEN / LTT), t0_s = (tile % (TLEN / LTT)) * LTT;
        u32 rb2h = sb + SM_B2 + zb * 18432;
        u32 rb2m = rb2h + 9216;
        u32 b2h_l4 = rb2h + lane * STR;
        u32 b2m_l4 = rb2m + lane * STR;
        int wb2h_off = SM_B2 + (zb ^ 1) * 18432;
        int wb2m_off = wb2h_off + 9216;
        u32 bufH = sb + gbuf * SM_BUF;
        u32 bufM = bufH + SM_B1M_OFF;
        u32 b1h_l4 = bufH + lane * STR;
        u32 b1m_l4 = bufM + lane * STR;
        u32 b1h_l2 = bufH + (lane & 15) * STR + 192 * STR;
        u32 b1m_l2 = bufM + (lane & 15) * STR + 192 * STR;
        float* skb = g_skips + (size_t)b_s * CH * TLEN;

#pragma unroll 1
        for (int j = 0; j < 8; ++j) {
            int ta = j * 16;
            /* --- skip MMAs (tile) first: short independent chains --- */
            float E0[4] = {0, 0, 0, 0}, E1[4] = {0, 0, 0, 0}, E2[4] = {0, 0, 0, 0};
            {
                u32 sh0[4], sm0[4], sh1[4], sm1[4];
                ldmT_x4(sh0, b2h_l4 + ta);
                ldmT_x4(sm0, b2m_l4 + ta);
                ldmT_x4(sh1, b2h_l4 + 32 * STR + ta);
                ldmT_x4(sm1, b2m_l4 + 32 * STR + ta);
                mma16816(E0, Zh[0], sh0);
                mma16816(E1, Zh[0], sm0);
                mma16816(E2, Zm[0], sh0);
                mma16816(E0, Zh[1], sh0 + 2);
                mma16816(E1, Zh[1], sm0 + 2);
                mma16816(E2, Zm[1], sh0 + 2);
                mma16816(E0, Zh[2], sh1);
                mma16816(E1, Zh[2], sm1);
                mma16816(E2, Zm[2], sh1);
                mma16816(E0, Zh[3], sh1 + 2);
                mma16816(E1, Zh[3], sm1 + 2);
                mma16816(E2, Zm[3], sh1 + 2);
            }
            /* --- gate MMAs (nt) --- */
            float D0[4] = {0, 0, 0, 0}, D1[4] = {0, 0, 0, 0}, D2[4] = {0, 0, 0, 0};
#pragma unroll
            for (int kk = 0; kk < 6; ++kk) {
                u32 bh[4], bm[4];
                ldmT_x4(bh, b1h_l4 + kk * 32 * STR + ta);
                ldmT_x4(bm, b1m_l4 + kk * 32 * STR + ta);
                mma16816(D0, Ah[2 * kk], bh);
                mma16816(D1, Ah[2 * kk], bm);
                mma16816(D2, Am[2 * kk], bh);
                mma16816(D0, Ah[2 * kk + 1], bh + 2);
                mma16816(D1, Ah[2 * kk + 1], bm + 2);
                mma16816(D2, Am[2 * kk + 1], bh + 2);
            }
            {
                u32 bh[2], bm[2];
                ldmT_x2(bh, b1h_l2 + ta);
                ldmT_x2(bm, b1m_l2 + ta);
                mma16816(D0, Ah[12], bh);
                mma16816(D1, Ah[12], bm);
                mma16816(D2, Am[12], bh);
            }
            /* --- gate activation -> B2[zb^1] --- */
            float a0 = D0[0] + D1[0] + D2[0] + ba;
            float a1 = D0[1] + D1[1] + D2[1] + ba;
            float g0 = D0[2] + D1[2] + D2[2] + bb;
            float g1 = D0[3] + D1[3] + D2[3] + bb;
            float z0 = gact(a0, g0), z1 = gact(a1, g1);
            int zoff = gch * STR + (j * 8 + lr * 2) * 2;
            *(u32*)(smc + wb2h_off + zoff) = pkbf(z0, z1);
            *(u32*)(smc + wb2m_off + zoff) = pkbf(z0 - bflo(z0), z1 - bflo(z1));
            /* --- skip epilogue (tile) --- */
            float e0 = E0[0] + E1[0] + E2[0] + bs0;
            float e1 = E0[1] + E1[1] + E2[1] + bs0;
            float e2 = E0[2] + E1[2] + E2[2] + bs1;
            float e3 = E0[3] + E1[3] + E2[3] + bs1;
            int tl = j * 8 + lr * 2;
            int t = t0_s + tl;
            if (r1 < 64) {
                float2 v0 = {e0, e1}, v1 = {e2, e3};
                if (!first_layer) {
                    float2 o0 = *(const float2*)(smc + SM_EPI_SK + r1 * 272 + tl * 4);
                    float2 o1 = *(const float2*)(smc + SM_EPI_SK + (r1 + 8) * 272 + tl * 4);
                    v0.x += o0.x; v0.y += o0.y; v1.x += o1.x; v1.y += o1.y;
                }
                *(float2*)(skb + (size_t)r1 * TLEN + t) = v0;
                *(float2*)(skb + (size_t)(r1 + 8) * TLEN + t) = v1;
            } else {
                int c0 = r1 - 64, c1 = c0 + 8;
                float2 i0h = upbf(*(const u32*)(smc + SM_EPI_HH + c0 * 144 + tl * 2));
                float2 i0m = upbf(*(const u32*)(smc + SM_EPI_HM + c0 * 144 + tl * 2));
                float2 i1h = upbf(*(const u32*)(smc + SM_EPI_HH + c1 * 144 + tl * 2));
                float2 i1m = upbf(*(const u32*)(smc + SM_EPI_HM + c1 * 144 + tl * 2));
                float v0 = e0 + i0h.x + i0m.x;
                float v1 = e1 + i0h.y + i0m.y;
                float v2 = e2 + i1h.x + i1m.x;
                float v3 = e3 + i1h.y + i1m.y;
                size_t a0i = (size_t)b_s * CH * TLEN + (size_t)c0 * TLEN + t;
                size_t a1i = (size_t)b_s * CH * TLEN + (size_t)c1 * TLEN + t;
                *(u32*)(qhh + a0i) = pkbf(v0, v1);
                *(u32*)(qhm + a0i) = pkbf(v0 - bflo(v0), v1 - bflo(v1));
                *(u32*)(qhh + a1i) = pkbf(v2, v3);
                *(u32*)(qhm + a1i) = pkbf(v2 - bflo(v2), v3 - bflo(v3));
            }
        }
        __syncthreads();   /* all epi readers done before re-staging */
        issue_epi(sb, nt, phh, phm, tid);
        CP_COMMIT();

        tile = nt; nt = nnt; gbuf ^= 1; zb ^= 1;
    }

    /* ---- final: skip(tile) with B2[zb] ---- */
    CP_WAIT0();
    __syncthreads();
    {
        int b_s = tile / (TLEN / LTT), t0_s = (tile % (TLEN / LTT)) * LTT;
        u32 rb2h = sb + SM_B2 + zb * 18432;
        u32 rb2m = rb2h + 9216;
        u32 b2h_l4 = rb2h + lane * STR;
        u32 b2m_l4 = rb2m + lane * STR;
        float* skb = g_skips + (size_t)b_s * CH * TLEN;
#pragma unroll 1
        for (int j = 0; j < 8; ++j) {
            float E0[4] = {0, 0, 0, 0}, E1[4] = {0, 0, 0, 0}, E2[4] = {0, 0, 0, 0};
            int ta = j * 16;
#pragma unroll
            for (int kk = 0; kk < 2; ++kk) {
                u32 bh[4], bm[4];
                ldmT_x4(bh, b2h_l4 + kk * 32 * STR + ta);
                ldmT_x4(bm, b2m_l4 + kk * 32 * STR + ta);
                mma16816(E0, Zh[2 * kk], bh);
                mma16816(E1, Zh[2 * kk], bm);
                mma16816(E2, Zm[2 * kk], bh);
                mma16816(E0, Zh[2 * kk + 1], bh + 2);
                mma16816(E1, Zh[2 * kk + 1], bm + 2);
                mma16816(E2, Zm[2 * kk + 1], bh + 2);
            }
            float e0 = E0[0] + E1[0] + E2[0] + bs0;
            float e1 = E0[1] + E1[1] + E2[1] + bs0;
            float e2 = E0[2] + E1[2] + E2[2] + bs1;
            float e3 = E0[3] + E1[3] + E2[3] + bs1;
            int tl = j * 8 + lr * 2;
            int t = t0_s + tl;
            if (r1 < 64) {
                float2 v0 = {e0, e1}, v1 = {e2, e3};
                if (!first_layer) {
                    float2 o0 = *(const float2*)(smc + SM_EPI_SK + r1 * 272 + tl * 4);
                    float2 o1 = *(const float2*)(smc + SM_EPI_SK + (r1 + 8) * 272 + tl * 4);
                    v0.x += o0.x; v0.y += o0.y; v1.x += o1.x; v1.y += o1.y;
                }
                *(float2*)(skb + (size_t)r1 * TLEN + t) = v0;
                *(float2*)(skb + (size_t)(r1 + 8) * TLEN + t) = v1;
            } else {
                int c0 = r1 - 64, c1 = c0 + 8;
                float2 i0h = upbf(*(const u32*)(smc + SM_EPI_HH + c0 * 144 + tl * 2));
                float2 i0m = upbf(*(const u32*)(smc + SM_EPI_HM + c0 * 144 + tl * 2));
                float2 i1h = upbf(*(const u32*)(smc + SM_EPI_HH + c1 * 144 + tl * 2));
                float2 i1m = upbf(*(const u32*)(smc + SM_EPI_HM + c1 * 144 + tl * 2));
                float v0 = e0 + i0h.x + i0m.x;
                float v1 = e1 + i0h.y + i0m.y;
                float v2 = e2 + i1h.x + i1m.x;
                float v3 = e3 + i1h.y + i1m.y;
                size_t a0i = (size_t)b_s * CH * TLEN + (size_t)c0 * TLEN + t;
                size_t a1i = (size_t)b_s * CH * TLEN + (size_t)c1 * TLEN + t;
                *(u32*)(qhh + a0i) = pkbf(v0, v1);
                *(u32*)(qhm + a0i) = pkbf(v0 - bflo(v0), v1 - bflo(v1));
                *(u32*)(qhh + a1i) = pkbf(v2, v3);
                *(u32*)(qhm + a1i) = pkbf(v2 - bflo(v2), v3 - bflo(v3));
            }
        }
    }
}

/* ---------------- last: relu,1x1,relu,1x1 (FFMA2) ---------------- */
__global__ void __launch_bounds__(256) last_kernel(const float* __restrict__ l1b,
                                                   const float* __restrict__ l2b,
                                                   float* __restrict__ out) {
    extern __shared__ float sm[];
    float* w1 = sm;
    float* w2 = sm + 4096;
    float* sk = sm + 20480;
    float* o1 = sm + 24576;
    for (int i = threadIdx.x; i < 4096 / 4; i += blockDim.x)
        ((float4*)w1)[i] = ((const float4*)g_wl1T)[i];
    for (int i = threadIdx.x; i < 16384 / 4; i += blockDim.x)
        ((float4*)w2)[i] = ((const float4*)g_wl2T)[i];
    int to = threadIdx.x & 15, oo = threadIdx.x >> 4;
    int tb = to * 4;
    for (int tile = blockIdx.x; tile < NTILES; tile += gridDim.x) {
        int b = tile / (TLEN / TT), t0 = (tile % (TLEN / TT)) * TT;
        __syncthreads();
        const float* skb = g_skips + (size_t)b * CH * TLEN;
        for (int i = threadIdx.x; i < CH * (TT / 4); i += blockDim.x) {
            int c = i / (TT / 4), q = i % (TT / 4);
            float4 v = *(const float4*)&skb[c * TLEN + t0 + q * 4];
            v.x = fmaxf(v.x, 0.f); v.y = fmaxf(v.y, 0.f);
            v.z = fmaxf(v.z, 0.f); v.w = fmaxf(v.w, 0.f);
            ((float4*)sk)[c * (TT / 4) + q] = v;
        }
        __syncthreads();
        {
            int ob = oo * 4;
            u64 acc[2][4];
#pragma unroll
            for (int op = 0; op < 2; ++op) {
                u64 bv = pk2(l1b[ob + 2 * op], l1b[ob + 2 * op + 1]);
#pragma unroll
                for (int ti = 0; ti < 4; ++ti) acc[op][ti] = bv;
            }
#pragma unroll 2
            for (int c = 0; c < 64; ++c) {
                float4 xv4 = *(const float4*)(sk + c * TT + tb);
                u64 xv[4] = {dup2f(xv4.x), dup2f(xv4.y), dup2f(xv4.z), dup2f(xv4.w)};
                ulonglong2 wv = *(const ulonglong2*)(w1 + c * 64 + ob);
                u64 wp[2] = {wv.x, wv.y};
#pragma unroll
                for (int op = 0; op < 2; ++op)
#pragma unroll
                    for (int ti = 0; ti < 4; ++ti) fma2(acc[op][ti], wp[op], xv[ti]);
            }
#pragma unroll
            for (int op = 0; op < 2; ++op) {
                float lo[4], hi[4];
#pragma unroll
                for (int ti = 0; ti < 4; ++ti) upk(lo[ti], hi[ti], acc[op][ti]);
                float4 v0 = {fmaxf(lo[0], 0.f), fmaxf(lo[1], 0.f), fmaxf(lo[2], 0.f), fmaxf(lo[3], 0.f)};
                float4 v1 = {fmaxf(hi[0], 0.f), fmaxf(hi[1], 0.f), fmaxf(hi[2], 0.f), fmaxf(hi[3], 0.f)};
                *(float4*)(o1 + (ob + 2 * op) * TT + tb) = v0;
                *(float4*)(o1 + (ob + 2 * op + 1) * TT + tb) = v1;
            }
        }
        __syncthreads();
        float* ob_out = out + (size_t)b * 256 * TLEN;
#pragma unroll
        for (int half = 0; half < 2; ++half) {
            int ob2 = half * 128 + oo * 8;
            u64 acc[4][4];
#pragma unroll
            for (int op = 0; op < 4; ++op) {
                u64 bv = pk2(l2b[ob2 + 2 * op], l2b[ob2 + 2 * op + 1]);
#pragma unroll
                for (int ti = 0; ti < 4; ++ti) acc[op][ti] = bv;
            }
#pragma unroll 2
            for (int c = 0; c < 64; ++c) {
                float4 zv4 = *(const float4*)(o1 + c * TT + tb);
                u64 zv[4] = {dup2f(zv4.x), dup2f(zv4.y), dup2f(zv4.z), dup2f(zv4.w)};
                ulonglong2 wa = *(const ulonglong2*)(w2 + c * 256 + ob2);
                ulonglong2 wb = *(const ulonglong2*)(w2 + c * 256 + ob2 + 4);
                u64 wp[4] = {wa.x, wa.y, wb.x, wb.y};
#pragma unroll
                for (int op = 0; op < 4; ++op)
#pragma unroll
                    for (int ti = 0; ti < 4; ++ti) fma2(acc[op][ti], wp[op], zv[ti]);
            }
#pragma unroll
            for (int op = 0; op < 4; ++op) {
                float lo[4], hi[4];
#pragma unroll
                for (int ti = 0; ti < 4; ++ti) upk(lo[ti], hi[ti], acc[op][ti]);
                float4 v0 = {lo[0], lo[1], lo[2], lo[3]};
                float4 v1 = {hi[0], hi[1], hi[2], hi[3]};
                *(float4*)&ob_out[(ob2 + 2 * op) * TLEN + t0 + tb] = v0;
                *(float4*)&ob_out[(ob2 + 2 * op + 1) * TLEN + t0 + tb] = v1;
            }
        }
    }
}

/* --------------------------------------------------------------- */
extern "C" void kernel_launch(void* const* d_in, const int* in_sizes, int n_in,
                              void* d_out, int out_size) {
    const float* x        = (const float*)d_in[0];
    const float* c        = (const float*)d_in[1];
    const float* first_w  = (const float*)d_in[2];
    const float* first_b  = (const float*)d_in[3];
    const float* conv_w   = (const float*)d_in[4];
    const float* conv_b   = (const float*)d_in[5];
    const float* cond_w   = (const float*)d_in[6];
    const float* out_w    = (const float*)d_in[7];
    const float* out_b    = (const float*)d_in[8];
    const float* skip_w   = (const float*)d_in[9];
    const float* skip_b   = (const float*)d_in[10];
    const float* last1_w  = (const float*)d_in[11];
    const float* last1_b  = (const float*)d_in[12];
    const float* last2_w  = (const float*)d_in[13];
    const float* last2_b  = (const float*)d_in[14];
    const float* conv_in_w= (const float*)d_in[15];
    const float* up_w0    = (const float*)d_in[16];
    const float* up_w1    = (const float*)d_in[17];
    float* out = (float*)d_out;

    int dev = 0;
    cudaGetDevice(&dev);
    int sms = 148;
    cudaDeviceGetAttribute(&sms, cudaDevAttrMultiProcessorCount, dev);

    cudaFuncSetAttribute(first_kernel, cudaFuncAttributeMaxDynamicSharedMemorySize, 131072);
    cudaFuncSetAttribute(layer_kernel, cudaFuncAttributeMaxDynamicSharedMemorySize, SM_TOTAL);
    cudaFuncSetAttribute(last_kernel,  cudaFuncAttributeMaxDynamicSharedMemorySize, 114688);

    {
        int total = NPG + NPZ + NPF;
        prep_all_kernel<<<(total + 255) / 256, 256>>>(
            conv_w, cond_w, skip_w, out_w, first_w, last1_w, last2_w);
    }
    cond_all_kernel<<<B_SZ * CCH, 256>>>(c, conv_in_w, up_w0, up_w1);
    first_kernel<<<sms, 256, 131072>>>(x, first_b);
    for (int l = 0; l < LAYERS; ++l) {
        int d = 1 << (l % 10);
        layer_kernel<<<sms, 256, SM_TOTAL>>>(l, d, l & 1, l == 0 ? 1 : 0,
                                             conv_b, skip_b, out_b);
    }
    last_kernel<<<sms, 256, 114688>>>(last1_b, last2_b, out);
}

// round 15
// speedup vs baseline: 1.0668x; 1.0668x over previous
#include <cuda_runtime.h>
#include <cuda_bf16.h>
#include <math.h>
#include <stdint.h>

#define LAYERS 30
#define B_SZ 4
#define TLEN 32000
#define TT 64
#define NTILES (B_SZ * (TLEN / TT))
#define LTT 64
#define LNT (B_SZ * (TLEN / LTT))   /* 2000 */
#define CH 64
#define CCH 80

/* layer SMEM: double B1, double B2, double epilogue staging */
#define STR 144
#define SM_BUF 59904              /* one B1 buffer: hi 29952 + mid 29952 */
#define SM_B1M_OFF 29952
#define SM_B2 119808              /* + q*18432 ; mid at +9216 */
#define SM_EPI 156672             /* + e*35840 ; SK at +0, HH +17408, HM +26624 */
#define EPI_STRIDE 35840
#define EPI_HH_OFF 17408
#define EPI_HM_OFF 26624
#define SM_TOTAL 228352

typedef unsigned long long u64;
typedef uint32_t u32;
typedef unsigned short u16;

__device__ __nv_bfloat16 g_hh[2][B_SZ * CH * TLEN];
__device__ __nv_bfloat16 g_hm[2][B_SZ * CH * TLEN];
__device__ float g_skips[B_SZ * CH * TLEN];
__device__ __nv_bfloat16 g_cbh[B_SZ * CCH * TLEN];
__device__ __nv_bfloat16 g_cbm[B_SZ * CCH * TLEN];
__device__ u32 g_gwh[LAYERS * 128 * 104];
__device__ u32 g_gwm[LAYERS * 128 * 104];
__device__ u32 g_wzh[LAYERS * 128 * 32];
__device__ u32 g_wzm[LAYERS * 128 * 32];
__device__ float g_wfirstT[256 * 64];
__device__ float g_wl1T[64 * 64];
__device__ float g_wl2T[64 * 256];

__device__ __forceinline__ u32 pkbf(float a, float b) {
    __nv_bfloat162 h = __floats2bfloat162_rn(a, b);
    return *reinterpret_cast<u32*>(&h);
}
__device__ __forceinline__ float bflo(float a) { return __bfloat162float(__float2bfloat16(a)); }
__device__ __forceinline__ float2 upbf(u32 v) {
    __nv_bfloat162 h = *reinterpret_cast<__nv_bfloat162*>(&v);
    return make_float2(__bfloat162float(h.x), __bfloat162float(h.y));
}
__device__ __forceinline__ float gact(float a, float b) {
    a = fmaxf(a, -15.f);
    b = fmaxf(b, -30.f);
    float e1 = __expf(-2.f * a);
    float e2 = __expf(-b);
    return (1.f - e1) * __fdividef(1.f, (1.f + e1) * (1.f + e2));
}

__device__ __forceinline__ u32 smem_u32(const void* p) {
    u32 a;
    asm("{ .reg .u64 t; cvta.to.shared.u64 t, %1; cvt.u32.u64 %0, t; }" : "=r"(a) : "l"(p));
    return a;
}
__device__ __forceinline__ void mma16816(float* d, const u32* a, const u32* b) {
    asm volatile("mma.sync.aligned.m16n8k16.row.col.f32.bf16.bf16.f32 "
        "{%0,%1,%2,%3}, {%4,%5,%6,%7}, {%8,%9}, {%0,%1,%2,%3};"
        : "+f"(d[0]), "+f"(d[1]), "+f"(d[2]), "+f"(d[3])
        : "r"(a[0]), "r"(a[1]), "r"(a[2]), "r"(a[3]), "r"(b[0]), "r"(b[1]));
}
__device__ __forceinline__ void ldmT_x4(u32* r, u32 addr) {
    asm volatile("ldmatrix.sync.aligned.m8n8.x4.trans.shared.b16 {%0,%1,%2,%3}, [%4];"
        : "=r"(r[0]), "=r"(r[1]), "=r"(r[2]), "=r"(r[3]) : "r"(addr));
}
__device__ __forceinline__ void ldmT_x2(u32* r, u32 addr) {
    asm volatile("ldmatrix.sync.aligned.m8n8.x2.trans.shared.b16 {%0,%1}, [%2];"
        : "=r"(r[0]), "=r"(r[1]) : "r"(addr));
}
#define CP16(dst, src) asm volatile("cp.async.cg.shared.global [%0], [%1], 16;" \
    :: "r"((u32)(dst)), "l"(src) : "memory")
#define CP8(dst, src)  asm volatile("cp.async.ca.shared.global [%0], [%1], 8;" \
    :: "r"((u32)(dst)), "l"(src) : "memory")
#define CP4(dst, src)  asm volatile("cp.async.ca.shared.global [%0], [%1], 4;" \
    :: "r"((u32)(dst)), "l"(src) : "memory")
#define CP_COMMIT() asm volatile("cp.async.commit_group;" ::: "memory")
#define CP_WAIT0()  asm volatile("cp.async.wait_group 0;" ::: "memory")
#define STS32(a, v) asm volatile("st.shared.b32 [%0], %1;" :: "r"((u32)(a)), "r"((u32)(v)) : "memory")

__device__ __forceinline__ u64 pk2(float lo, float hi) {
    u64 r; asm("mov.b64 %0, {%1, %2};" : "=l"(r) : "f"(lo), "f"(hi)); return r;
}
__device__ __forceinline__ u64 dup2f(float v) { return pk2(v, v); }
__device__ __forceinline__ void fma2(u64& d, u64 a, u64 b) {
    asm("fma.rn.f32x2 %0, %1, %2, %0;" : "+l"(d) : "l"(a), "l"(b));
}
__device__ __forceinline__ void upk(float& lo, float& hi, u64 v) {
    asm("mov.b64 {%0, %1}, %2;" : "=f"(lo), "=f"(hi) : "l"(v));
}

__device__ __forceinline__ int orig_gate_row(int r) {
    int q = r >> 4, i = r & 15;
    return (i < 8) ? (8 * q + i) : (64 + 8 * q + (i - 8));
}

/* ---------------- merged weight prep ---------------- */
#define NPG (LAYERS * 128 * 104)
#define NPZ (LAYERS * 128 * 32)
#define NPF (16384 + 4096 + 16384)
__global__ void prep_all_kernel(const float* __restrict__ conv_w,
                                const float* __restrict__ cond_w,
                                const float* __restrict__ skip_w,
                                const float* __restrict__ out_w,
                                const float* __restrict__ first_w,
                                const float* __restrict__ last1_w,
                                const float* __restrict__ last2_w) {
    int idx = blockIdx.x * blockDim.x + threadIdx.x;
    if (idx < NPG) {
        int l = idx / (128 * 104), rem = idx % (128 * 104);
        int r = rem / 104, kp = rem % 104;
        int o = orig_gate_row(r);
        float w[2];
#pragma unroll
        for (int e = 0; e < 2; ++e) {
            int k = 2 * kp + e;
            if (k < 64)       w[e] = conv_w[((l * 128 + o) * 64 + k) * 2 + 0];
            else if (k < 128) w[e] = conv_w[((l * 128 + o) * 64 + (k - 64)) * 2 + 1];
            else              w[e] = cond_w[(l * 128 + o) * 80 + (k - 128)];
        }
        g_gwh[idx] = pkbf(w[0], w[1]);
        g_gwm[idx] = pkbf(w[0] - bflo(w[0]), w[1] - bflo(w[1]));
    } else if (idx < NPG + NPZ) {
        int j = idx - NPG;
        int l = j / (128 * 32), rem = j % (128 * 32);
        int r = rem / 32, kp = rem % 32;
        float w[2];
#pragma unroll
        for (int e = 0; e < 2; ++e) {
            int k = 2 * kp + e;
            w[e] = (r < 64) ? skip_w[(l * 64 + r) * 64 + k]
                            : out_w[(l * 64 + (r - 64)) * 64 + k];
        }
        g_wzh[j] = pkbf(w[0], w[1]);
        g_wzm[j] = pkbf(w[0] - bflo(w[0]), w[1] - bflo(w[1]));
    } else if (idx < NPG + NPZ + NPF) {
        int j = idx - NPG - NPZ;
        if (j < 16384) {
            int c = j >> 6, o = j & 63;
            g_wfirstT[j] = first_w[o * 256 + c];
        } else if (j < 16384 + 4096) {
            int jj = j - 16384; int c = jj >> 6, o = jj & 63;
            g_wl1T[jj] = last1_w[o * 64 + c];
        } else {
            int jj = j - 16384 - 4096; int c = jj >> 8, o = jj & 255;
            g_wl2T[jj] = last2_w[o * 64 + c];
        }
    }
}

/* ---------------- merged conditioning ---------------- */
__global__ void __launch_bounds__(256) cond_all_kernel(
        const float* __restrict__ cin, const float* __restrict__ conv_in_w,
        const float* __restrict__ w0, const float* __restrict__ w1) {
    __shared__ float c1row[400];
    __shared__ float c2row[4000];
    int blk = blockIdx.x;
    int b = blk / CCH, o = blk % CCH;
    int tid = threadIdx.x;
    for (int f = tid; f < 400; f += 256) {
        const float* src = cin + (size_t)(b * CCH) * 400 + f;
        float acc = 0.f;
#pragma unroll 8
        for (int ch = 0; ch < 80; ++ch)
            acc += __ldg(&conv_in_w[o * 80 + ch]) * __ldg(&src[ch * 400]);
        c1row[f] = acc;
    }
    __syncthreads();
    for (int t = tid; t < 4000; t += 256) {
        float acc = 0.f;
        int base = t - 10;
        for (int j = 0; j < 21; ++j) {
            int u = base + j;
            if (u >= 0 && u < 4000) acc += __ldg(&w0[j]) * c1row[u / 10];
        }
        c2row[t] = acc;
    }
    __syncthreads();
    size_t rowoff = (size_t)(b * CCH + o) * TLEN;
    for (int t = tid; t < TLEN; t += 256) {
        float acc = 0.f;
        int base = t - 8;
        for (int j = 0; j < 17; ++j) {
            int u = base + j;
            if (u >= 0 && u < TLEN) acc += __ldg(&w1[j]) * c2row[u / 8];
        }
        g_cbh[rowoff + t] = __float2bfloat16(acc);
        g_cbm[rowoff + t] = __float2bfloat16(acc - bflo(acc));
    }
}

/* ---------------- first 1x1 conv (FFMA2) -> bf16 hi/mid planes ------------- */
__global__ void __launch_bounds__(256) first_kernel(const float* __restrict__ x,
                                                    const float* __restrict__ first_b) {
    extern __shared__ float sm[];
    float* xs = sm;
    float* wf = sm + 16384;
    for (int i = threadIdx.x; i < 16384 / 4; i += blockDim.x)
        ((float4*)wf)[i] = ((const float4*)g_wfirstT)[i];
    int to = threadIdx.x & 15, oo = threadIdx.x >> 4;
    int tb = to * 4, ob = oo * 4;
    for (int tile = blockIdx.x; tile < NTILES; tile += gridDim.x) {
        int b = tile / (TLEN / TT), t0 = (tile % (TLEN / TT)) * TT;
        __syncthreads();
        const float* xb = x + (size_t)b * 256 * TLEN;
        for (int i = threadIdx.x; i < 256 * (TT / 4); i += blockDim.x) {
            int c = i / (TT / 4), q = i % (TT / 4);
            ((float4*)xs)[c * (TT / 4) + q] = *(const float4*)&xb[c * TLEN + t0 + q * 4];
        }
        __syncthreads();
        u64 acc[2][4];
#pragma unroll
        for (int op = 0; op < 2; ++op) {
            u64 bv = pk2(first_b[ob + 2 * op], first_b[ob + 2 * op + 1]);
#pragma unroll
            for (int ti = 0; ti < 4; ++ti) acc[op][ti] = bv;
        }
#pragma unroll 2
        for (int c = 0; c < 256; ++c) {
            float4 xv4 = *(const float4*)(xs + c * TT + tb);
            u64 xv[4] = {dup2f(xv4.x), dup2f(xv4.y), dup2f(xv4.z), dup2f(xv4.w)};
            ulonglong2 wv = *(const ulonglong2*)(wf + c * 64 + ob);
            u64 w2[2] = {wv.x, wv.y};
#pragma unroll
            for (int op = 0; op < 2; ++op)
#pragma unroll
                for (int ti = 0; ti < 4; ++ti) fma2(acc[op][ti], w2[op], xv[ti]);
        }
        __nv_bfloat16* hh = g_hh[0] + (size_t)b * CH * TLEN;
        __nv_bfloat16* hm = g_hm[0] + (size_t)b * CH * TLEN;
#pragma unroll
        for (int op = 0; op < 2; ++op) {
            float lo[4], hi[4];
#pragma unroll
            for (int ti = 0; ti < 4; ++ti) upk(lo[ti], hi[ti], acc[op][ti]);
            int r0 = ob + 2 * op, r1 = r0 + 1;
            u32* p;
            p = (u32*)(hh + (size_t)r0 * TLEN + t0 + tb);
            p[0] = pkbf(lo[0], lo[1]); p[1] = pkbf(lo[2], lo[3]);
            p = (u32*)(hm + (size_t)r0 * TLEN + t0 + tb);
            p[0] = pkbf(lo[0] - bflo(lo[0]), lo[1] - bflo(lo[1]));
            p[1] = pkbf(lo[2] - bflo(lo[2]), lo[3] - bflo(lo[3]));
            p = (u32*)(hh + (size_t)r1 * TLEN + t0 + tb);
            p[0] = pkbf(hi[0], hi[1]); p[1] = pkbf(hi[2], hi[3]);
            p = (u32*)(hm + (size_t)r1 * TLEN + t0 + tb);
            p[0] = pkbf(hi[0] - bflo(hi[0]), hi[1] - bflo(hi[1]));
            p[1] = pkbf(hi[2] - bflo(hi[2]), hi[3] - bflo(hi[3]));
        }
    }
}

/* ---- async B1 issue ---- */
__device__ __forceinline__ void issue_b1(char* smc, u32 sb, u32 bufoff, int tile,
                                         int d, const __nv_bfloat16* phh,
                                         const __nv_bfloat16* phm, int tid) {
    int b = tile / (TLEN / LTT), t0 = (tile % (TLEN / LTT)) * LTT;
    const __nv_bfloat16* hbh = phh + (size_t)b * CH * TLEN;
    const __nv_bfloat16* hbm = phm + (size_t)b * CH * TLEN;
    u32 dsth = sb + bufoff;
    u32 dstm = dsth + SM_B1M_OFF;
    for (int i = tid; i < 144 * 8; i += 256) {
        int r = i >> 3, g = i & 7;
        const __nv_bfloat16 *s1, *s2;
        if (r < 64) {
            size_t a = (size_t)r * TLEN + t0 + g * 8;
            s1 = hbh + a; s2 = hbm + a;
        } else {
            size_t a = ((size_t)(b * CCH + r - 64)) * TLEN + t0 + g * 8;
            s1 = g_cbh + a; s2 = g_cbm + a;
        }
        u32 off = (u32)((64 + r) * STR + g * 16);
        CP16(dsth + off, s1);
        CP16(dstm + off, s2);
    }
    for (int i = tid; i < 64 * 8; i += 256) {
        int r = i >> 3, g = i & 7;
        int tg = t0 - d + g * 8;
        const __nv_bfloat16* sh = hbh + (size_t)r * TLEN;
        const __nv_bfloat16* sm2 = hbm + (size_t)r * TLEN;
        u32 off = (u32)(r * STR + g * 16);
        if (tg >= 0 && d >= 8) {
            CP16(dsth + off, sh + tg);
            CP16(dstm + off, sm2 + tg);
        } else if (tg >= 0 && d == 4) {
            CP8(dsth + off, sh + tg);      CP8(dsth + off + 8, sh + tg + 4);
            CP8(dstm + off, sm2 + tg);     CP8(dstm + off + 8, sm2 + tg + 4);
        } else if (tg >= 0 && d == 2) {
#pragma unroll
            for (int q = 0; q < 4; ++q) {
                CP4(dsth + off + q * 4, sh + tg + q * 2);
                CP4(dstm + off + q * 4, sm2 + tg + q * 2);
            }
        } else {
#pragma unroll
            for (int e = 0; e < 4; ++e) {
                int tt0 = tg + 2 * e, tt1 = tt0 + 1;
                u16 h0 = (tt0 >= 0) ? *(const u16*)(sh + tt0) : 0;
                u16 h1 = (tt1 >= 0) ? *(const u16*)(sh + tt1) : 0;
                u16 m0 = (tt0 >= 0) ? *(const u16*)(sm2 + tt0) : 0;
                u16 m1 = (tt1 >= 0) ? *(const u16*)(sm2 + tt1) : 0;
                STS32(dsth + off + e * 4, (u32)h0 | ((u32)h1 << 16));
                STS32(dstm + off + e * 4, (u32)m0 | ((u32)m1 << 16));
            }
        }
    }
}

/* ---- async epilogue staging into buffer eb ---- */
__device__ __forceinline__ void issue_epi(u32 sb, int eb, int tile,
                                          const __nv_bfloat16* phh,
                                          const __nv_bfloat16* phm, int tid) {
    int b = tile / (TLEN / LTT), t0 = (tile % (TLEN / LTT)) * LTT;
    const float* skb = g_skips + (size_t)b * CH * TLEN;
    const __nv_bfloat16* hbh = phh + (size_t)b * CH * TLEN;
    const __nv_bfloat16* hbm = phm + (size_t)b * CH * TLEN;
    u32 base = sb + SM_EPI + (u32)eb * EPI_STRIDE;
    for (int i = tid; i < 1024; i += 256) {
        int r = i >> 4, g = i & 15;
        CP16(base + r * 272 + g * 16, skb + (size_t)r * TLEN + t0 + g * 4);
    }
    for (int i = tid; i < 512; i += 256) {
        int r = i >> 3, g = i & 7;
        CP16(base + EPI_HH_OFF + r * 144 + g * 16, hbh + (size_t)r * TLEN + t0 + g * 8);
        CP16(base + EPI_HM_OFF + r * 144 + g * 16, hbm + (size_t)r * TLEN + t0 + g * 8);
    }
}

/* ---------------- fused residual layer: pipelined, 1 sync/tile ------------- */
__global__ void __launch_bounds__(256, 1) layer_kernel(int l, int d, int hin, int first_layer,
        const float* __restrict__ conv_b, const float* __restrict__ skip_b,
        const float* __restrict__ out_b) {
    extern __shared__ char smc[];
    u32 sb = smem_u32(smc);
    int tid = threadIdx.x, w = tid >> 5, lane = tid & 31;
    int lq = lane >> 2, lr = lane & 3;

    u32 Ah[13][4], Am[13][4], Zh[4][4], Zm[4][4];
    {
        const u32* gh = g_gwh + ((size_t)l * 128 + 16 * w) * 104;
        const u32* gm = g_gwm + ((size_t)l * 128 + 16 * w) * 104;
#pragma unroll
        for (int ks = 0; ks < 13; ++ks) {
            int kp = 8 * ks + lr;
            Ah[ks][0] = gh[lq * 104 + kp];     Ah[ks][1] = gh[(8 + lq) * 104 + kp];
            Ah[ks][2] = gh[lq * 104 + kp + 4]; Ah[ks][3] = gh[(8 + lq) * 104 + kp + 4];
            Am[ks][0] = gm[lq * 104 + kp];     Am[ks][1] = gm[(8 + lq) * 104 + kp];
            Am[ks][2] = gm[lq * 104 + kp + 4]; Am[ks][3] = gm[(8 + lq) * 104 + kp + 4];
        }
        const u32* zh = g_wzh + ((size_t)l * 128 + 16 * w) * 32;
        const u32* zm = g_wzm + ((size_t)l * 128 + 16 * w) * 32;
#pragma unroll
        for (int ks = 0; ks < 4; ++ks) {
            int kp = 8 * ks + lr;
            Zh[ks][0] = zh[lq * 32 + kp];     Zh[ks][1] = zh[(8 + lq) * 32 + kp];
            Zh[ks][2] = zh[lq * 32 + kp + 4]; Zh[ks][3] = zh[(8 + lq) * 32 + kp + 4];
            Zm[ks][0] = zm[lq * 32 + kp];     Zm[ks][1] = zm[(8 + lq) * 32 + kp];
            Zm[ks][2] = zm[lq * 32 + kp + 4]; Zm[ks][3] = zm[(8 + lq) * 32 + kp + 4];
        }
    }
    int gch = 8 * w + lq;
    float ba = conv_b[l * 128 + gch];
    float bb = conv_b[l * 128 + 64 + gch];
    int r1 = 16 * w + lq;
    float bs0 = (r1 < 64) ? skip_b[l * 64 + r1] : out_b[l * 64 + r1 - 64];
    float bs1 = (r1 < 64) ? skip_b[l * 64 + r1 + 8] : out_b[l * 64 + r1 - 56];

    const __nv_bfloat16* phh = g_hh[hin];
    const __nv_bfloat16* phm = g_hm[hin];
    __nv_bfloat16* qhh = g_hh[hin ^ 1];
    __nv_bfloat16* qhm = g_hm[hin ^ 1];

    int tile = blockIdx.x;
    if (tile >= LNT) return;

    /* prologue: B1(T0) */
    issue_b1(smc, sb, 0, tile, d, phh, phm, tid);
    CP_COMMIT();
    CP_WAIT0();
    __syncthreads();

    /* issue B1(T1) + epi[0](T0) in one group */
    int nt = tile + gridDim.x;
    if (nt < LNT)
        issue_b1(smc, sb, SM_BUF, nt, d, phh, phm, tid);
    issue_epi(sb, 0, tile, phh, phm, tid);
    CP_COMMIT();

    /* peel: gate(T0) from buf0 -> B2[0] */
    {
        u32 bufH = sb;
        u32 bufM = bufH + SM_B1M_OFF;
        u32 b1h_l4 = bufH + lane * STR;
        u32 b1m_l4 = bufM + lane * STR;
        u32 b1h_l2 = bufH + (lane & 15) * STR + 192 * STR;
        u32 b1m_l2 = bufM + (lane & 15) * STR + 192 * STR;
        int wb2h_off = SM_B2, wb2m_off = SM_B2 + 9216;
#pragma unroll 1
        for (int j = 0; j < 8; ++j) {
            float D0[4] = {0, 0, 0, 0}, D1[4] = {0, 0, 0, 0}, D2[4] = {0, 0, 0, 0};
            int ta = j * 16;
#pragma unroll
            for (int kk = 0; kk < 6; ++kk) {
                u32 bh[4], bm[4];
                ldmT_x4(bh, b1h_l4 + kk * 32 * STR + ta);
                ldmT_x4(bm, b1m_l4 + kk * 32 * STR + ta);
                mma16816(D0, Ah[2 * kk], bh);
                mma16816(D1, Ah[2 * kk], bm);
                mma16816(D2, Am[2 * kk], bh);
                mma16816(D0, Ah[2 * kk + 1], bh + 2);
                mma16816(D1, Ah[2 * kk + 1], bm + 2);
                mma16816(D2, Am[2 * kk + 1], bh + 2);
            }
            {
                u32 bh[2], bm[2];
                ldmT_x2(bh, b1h_l2 + ta);
                ldmT_x2(bm, b1m_l2 + ta);
                mma16816(D0, Ah[12], bh);
                mma16816(D1, Ah[12], bm);
                mma16816(D2, Am[12], bh);
            }
            float a0 = D0[0] + D1[0] + D2[0] + ba;
            float a1 = D0[1] + D1[1] + D2[1] + ba;
            float g0 = D0[2] + D1[2] + D2[2] + bb;
            float g1 = D0[3] + D1[3] + D2[3] + bb;
            float z0 = gact(a0, g0), z1 = gact(a1, g1);
            int zoff = gch * STR + (j * 8 + lr * 2) * 2;
            *(u32*)(smc + wb2h_off + zoff) = pkbf(z0, z1);
            *(u32*)(smc + wb2m_off + zoff) = pkbf(z0 - bflo(z0), z1 - bflo(z1));
        }
    }

    int gbuf = 1, zb = 0, eb = 0;

    /* ---- main loop: skip(tile) + gate(nt), one sync per tile ---- */
    while (nt < LNT) {
        CP_WAIT0();
        __syncthreads();   /* B1(nt) + epi[eb](tile) landed; B2[zb] visible */

        int nnt = nt + gridDim.x;
        if (nnt < LNT)
            issue_b1(smc, sb, (u32)((gbuf ^ 1) * SM_BUF), nnt, d, phh, phm, tid);
        issue_epi(sb, eb ^ 1, nt, phh, phm, tid);
        CP_COMMIT();

        int b_s = tile / (TLEN / LTT), t0_s = (tile % (TLEN / LTT)) * LTT;
        u32 rb2h = sb + SM_B2 + zb * 18432;
        u32 rb2m = rb2h + 9216;
        u32 b2h_l4 = rb2h + lane * STR;
        u32 b2m_l4 = rb2m + lane * STR;
        int wb2h_off = SM_B2 + (zb ^ 1) * 18432;
        int wb2m_off = wb2h_off + 9216;
        u32 bufH = sb + gbuf * SM_BUF;
        u32 bufM = bufH + SM_B1M_OFF;
        u32 b1h_l4 = bufH + lane * STR;
        u32 b1m_l4 = bufM + lane * STR;
        u32 b1h_l2 = bufH + (lane & 15) * STR + 192 * STR;
        u32 b1m_l2 = bufM + (lane & 15) * STR + 192 * STR;
        u32 epiB = sb + SM_EPI + (u32)eb * EPI_STRIDE;
        float* skb = g_skips + (size_t)b_s * CH * TLEN;

#pragma unroll 1
        for (int j = 0; j < 8; ++j) {
            int ta = j * 16;
            float E0[4] = {0, 0, 0, 0}, E1[4] = {0, 0, 0, 0}, E2[4] = {0, 0, 0, 0};
            {
                u32 sh0[4], sm0[4], sh1[4], sm1[4];
                ldmT_x4(sh0, b2h_l4 + ta);
                ldmT_x4(sm0, b2m_l4 + ta);
                ldmT_x4(sh1, b2h_l4 + 32 * STR + ta);
                ldmT_x4(sm1, b2m_l4 + 32 * STR + ta);
                mma16816(E0, Zh[0], sh0);
                mma16816(E1, Zh[0], sm0);
                mma16816(E2, Zm[0], sh0);
                mma16816(E0, Zh[1], sh0 + 2);
                mma16816(E1, Zh[1], sm0 + 2);
                mma16816(E2, Zm[1], sh0 + 2);
                mma16816(E0, Zh[2], sh1);
                mma16816(E1, Zh[2], sm1);
                mma16816(E2, Zm[2], sh1);
                mma16816(E0, Zh[3], sh1 + 2);
                mma16816(E1, Zh[3], sm1 + 2);
                mma16816(E2, Zm[3], sh1 + 2);
            }
            float D0[4] = {0, 0, 0, 0}, D1[4] = {0, 0, 0, 0}, D2[4] = {0, 0, 0, 0};
#pragma unroll
            for (int kk = 0; kk < 6; ++kk) {
                u32 bh[4], bm[4];
                ldmT_x4(bh, b1h_l4 + kk * 32 * STR + ta);
                ldmT_x4(bm, b1m_l4 + kk * 32 * STR + ta);
                mma16816(D0, Ah[2 * kk], bh);
                mma16816(D1, Ah[2 * kk], bm);
                mma16816(D2, Am[2 * kk], bh);
                mma16816(D0, Ah[2 * kk + 1], bh + 2);
                mma16816(D1, Ah[2 * kk + 1], bm + 2);
                mma16816(D2, Am[2 * kk + 1], bh + 2);
            }
            {
                u32 bh[2], bm[2];
                ldmT_x2(bh, b1h_l2 + ta);
                ldmT_x2(bm, b1m_l2 + ta);
                mma16816(D0, Ah[12], bh);
                mma16816(D1, Ah[12], bm);
                mma16816(D2, Am[12], bh);
            }
            float a0 = D0[0] + D1[0] + D2[0] + ba;
            float a1 = D0[1] + D1[1] + D2[1] + ba;
            float g0 = D0[2] + D1[2] + D2[2] + bb;
            float g1 = D0[3] + D1[3] + D2[3] + bb;
            float z0 = gact(a0, g0), z1 = gact(a1, g1);
            int zoff = gch * STR + (j * 8 + lr * 2) * 2;
            *(u32*)(smc + wb2h_off + zoff) = pkbf(z0, z1);
            *(u32*)(smc + wb2m_off + zoff) = pkbf(z0 - bflo(z0), z1 - bflo(z1));
            float e0 = E0[0] + E1[0] + E2[0] + bs0;
            float e1 = E0[1] + E1[1] + E2[1] + bs0;
            float e2 = E0[2] + E1[2] + E2[2] + bs1;
            float e3 = E0[3] + E1[3] + E2[3] + bs1;
            int tl = j * 8 + lr * 2;
            int t = t0_s + tl;
            if (r1 < 64) {
                float2 v0 = {e0, e1}, v1 = {e2, e3};
                if (!first_layer) {
                    float2 o0 = *(const float2*)(smc + (epiB - sb) + r1 * 272 + tl * 4);
                    float2 o1 = *(const float2*)(smc + (epiB - sb) + (r1 + 8) * 272 + tl * 4);
                    v0.x += o0.x; v0.y += o0.y; v1.x += o1.x; v1.y += o1.y;
                }
                *(float2*)(skb + (size_t)r1 * TLEN + t) = v0;
                *(float2*)(skb + (size_t)(r1 + 8) * TLEN + t) = v1;
            } else {
                int c0 = r1 - 64, c1 = c0 + 8;
                const char* eB = smc + (epiB - sb);
                float2 i0h = upbf(*(const u32*)(eB + EPI_HH_OFF + c0 * 144 + tl * 2));
                float2 i0m = upbf(*(const u32*)(eB + EPI_HM_OFF + c0 * 144 + tl * 2));
                float2 i1h = upbf(*(const u32*)(eB + EPI_HH_OFF + c1 * 144 + tl * 2));
                float2 i1m = upbf(*(const u32*)(eB + EPI_HM_OFF + c1 * 144 + tl * 2));
                float v0 = e0 + i0h.x + i0m.x;
                float v1 = e1 + i0h.y + i0m.y;
                float v2 = e2 + i1h.x + i1m.x;
                float v3 = e3 + i1h.y + i1m.y;
                size_t a0i = (size_t)b_s * CH * TLEN + (size_t)c0 * TLEN + t;
                size_t a1i = (size_t)b_s * CH * TLEN + (size_t)c1 * TLEN + t;
                *(u32*)(qhh + a0i) = pkbf(v0, v1);
                *(u32*)(qhm + a0i) = pkbf(v0 - bflo(v0), v1 - bflo(v1));
                *(u32*)(qhh + a1i) = pkbf(v2, v3);
                *(u32*)(qhm + a1i) = pkbf(v2 - bflo(v2), v3 - bflo(v3));
            }
        }
        tile = nt; nt = nnt; gbuf ^= 1; zb ^= 1; eb ^= 1;
    }

    /* ---- final: skip(tile) with B2[zb], epi[eb] ---- */
    CP_WAIT0();
    __syncthreads();
    {
        int b_s = tile / (TLEN / LTT), t0_s = (tile % (TLEN / LTT)) * LTT;
        u32 rb2h = sb + SM_B2 + zb * 18432;
        u32 rb2m = rb2h + 9216;
        u32 b2h_l4 = rb2h + lane * STR;
        u32 b2m_l4 = rb2m + lane * STR;
        const char* eB = smc + SM_EPI + eb * EPI_STRIDE;
        float* skb = g_skips + (size_t)b_s * CH * TLEN;
#pragma unroll 1
        for (int j = 0; j < 8; ++j) {
            float E0[4] = {0, 0, 0, 0}, E1[4] = {0, 0, 0, 0}, E2[4] = {0, 0, 0, 0};
            int ta = j * 16;
#pragma unroll
            for (int kk = 0; kk < 2; ++kk) {
                u32 bh[4], bm[4];
                ldmT_x4(bh, b2h_l4 + kk * 32 * STR + ta);
                ldmT_x4(bm, b2m_l4 + kk * 32 * STR + ta);
                mma16816(E0, Zh[2 * kk], bh);
                mma16816(E1, Zh[2 * kk], bm);
                mma16816(E2, Zm[2 * kk], bh);
                mma16816(E0, Zh[2 * kk + 1], bh + 2);
                mma16816(E1, Zh[2 * kk + 1], bm + 2);
                mma16816(E2, Zm[2 * kk + 1], bh + 2);
            }
            float e0 = E0[0] + E1[0] + E2[0] + bs0;
            float e1 = E0[1] + E1[1] + E2[1] + bs0;
            float e2 = E0[2] + E1[2] + E2[2] + bs1;
            float e3 = E0[3] + E1[3] + E2[3] + bs1;
            int tl = j * 8 + lr * 2;
            int t = t0_s + tl;
            if (r1 < 64) {
                float2 v0 = {e0, e1}, v1 = {e2, e3};
                if (!first_layer) {
                    float2 o0 = *(const float2*)(eB + r1 * 272 + tl * 4);
                    float2 o1 = *(const float2*)(eB + (r1 + 8) * 272 + tl * 4);
                    v0.x += o0.x; v0.y += o0.y; v1.x += o1.x; v1.y += o1.y;
                }
                *(float2*)(skb + (size_t)r1 * TLEN + t) = v0;
                *(float2*)(skb + (size_t)(r1 + 8) * TLEN + t) = v1;
            } else {
                int c0 = r1 - 64, c1 = c0 + 8;
                float2 i0h = upbf(*(const u32*)(eB + EPI_HH_OFF + c0 * 144 + tl * 2));
                float2 i0m = upbf(*(const u32*)(eB + EPI_HM_OFF + c0 * 144 + tl * 2));
                float2 i1h = upbf(*(const u32*)(eB + EPI_HH_OFF + c1 * 144 + tl * 2));
                float2 i1m = upbf(*(const u32*)(eB + EPI_HM_OFF + c1 * 144 + tl * 2));
                float v0 = e0 + i0h.x + i0m.x;
                float v1 = e1 + i0h.y + i0m.y;
                float v2 = e2 + i1h.x + i1m.x;
                float v3 = e3 + i1h.y + i1m.y;
                size_t a0i = (size_t)b_s * CH * TLEN + (size_t)c0 * TLEN + t;
                size_t a1i = (size_t)b_s * CH * TLEN + (size_t)c1 * TLEN + t;
                *(u32*)(qhh + a0i) = pkbf(v0, v1);
                *(u32*)(qhm + a0i) = pkbf(v0 - bflo(v0), v1 - bflo(v1));
                *(u32*)(qhh + a1i) = pkbf(v2, v3);
                *(u32*)(qhm + a1i) = pkbf(v2 - bflo(v2), v3 - bflo(v3));
            }
        }
    }
}

/* ---------------- last: relu,1x1,relu,1x1 (FFMA2) ---------------- */
__global__ void __launch_bounds__(256) last_kernel(const float* __restrict__ l1b,
                                                   const float* __restrict__ l2b,
                                                   float* __restrict__ out) {
    extern __shared__ float sm[];
    float* w1 = sm;
    float* w2 = sm + 4096;
    float* sk = sm + 20480;
    float* o1 = sm + 24576;
    for (int i = threadIdx.x; i < 4096 / 4; i += blockDim.x)
        ((float4*)w1)[i] = ((const float4*)g_wl1T)[i];
    for (int i = threadIdx.x; i < 16384 / 4; i += blockDim.x)
        ((float4*)w2)[i] = ((const float4*)g_wl2T)[i];
    int to = threadIdx.x & 15, oo = threadIdx.x >> 4;
    int tb = to * 4;
    for (int tile = blockIdx.x; tile < NTILES; tile += gridDim.x) {
        int b = tile / (TLEN / TT), t0 = (tile % (TLEN / TT)) * TT;
        __syncthreads();
        const float* skb = g_skips + (size_t)b * CH * TLEN;
        for (int i = threadIdx.x; i < CH * (TT / 4); i += blockDim.x) {
            int c = i / (TT / 4), q = i % (TT / 4);
            float4 v = *(const float4*)&skb[c * TLEN + t0 + q * 4];
            v.x = fmaxf(v.x, 0.f); v.y = fmaxf(v.y, 0.f);
            v.z = fmaxf(v.z, 0.f); v.w = fmaxf(v.w, 0.f);
            ((float4*)sk)[c * (TT / 4) + q] = v;
        }
        __syncthreads();
        {
            int ob = oo * 4;
            u64 acc[2][4];
#pragma unroll
            for (int op = 0; op < 2; ++op) {
                u64 bv = pk2(l1b[ob + 2 * op], l1b[ob + 2 * op + 1]);
#pragma unroll
                for (int ti = 0; ti < 4; ++ti) acc[op][ti] = bv;
            }
#pragma unroll 2
            for (int c = 0; c < 64; ++c) {
                float4 xv4 = *(const float4*)(sk + c * TT + tb);
                u64 xv[4] = {dup2f(xv4.x), dup2f(xv4.y), dup2f(xv4.z), dup2f(xv4.w)};
                ulonglong2 wv = *(const ulonglong2*)(w1 + c * 64 + ob);
                u64 wp[2] = {wv.x, wv.y};
#pragma unroll
                for (int op = 0; op < 2; ++op)
#pragma unroll
                    for (int ti = 0; ti < 4; ++ti) fma2(acc[op][ti], wp[op], xv[ti]);
            }
#pragma unroll
            for (int op = 0; op < 2; ++op) {
                float lo[4], hi[4];
#pragma unroll
                for (int ti = 0; ti < 4; ++ti) upk(lo[ti], hi[ti], acc[op][ti]);
                float4 v0 = {fmaxf(lo[0], 0.f), fmaxf(lo[1], 0.f), fmaxf(lo[2], 0.f), fmaxf(lo[3], 0.f)};
                float4 v1 = {fmaxf(hi[0], 0.f), fmaxf(hi[1], 0.f), fmaxf(hi[2], 0.f), fmaxf(hi[3], 0.f)};
                *(float4*)(o1 + (ob + 2 * op) * TT + tb) = v0;
                *(float4*)(o1 + (ob + 2 * op + 1) * TT + tb) = v1;
            }
        }
        __syncthreads();
        float* ob_out = out + (size_t)b * 256 * TLEN;
#pragma unroll
        for (int half = 0; half < 2; ++half) {
            int ob2 = half * 128 + oo * 8;
            u64 acc[4][4];
#pragma unroll
            for (int op = 0; op < 4; ++op) {
                u64 bv = pk2(l2b[ob2 + 2 * op], l2b[ob2 + 2 * op + 1]);
#pragma unroll
                for (int ti = 0; ti < 4; ++ti) acc[op][ti] = bv;
            }
#pragma unroll 2
            for (int c = 0; c < 64; ++c) {
                float4 zv4 = *(const float4*)(o1 + c * TT + tb);
                u64 zv[4] = {dup2f(zv4.x), dup2f(zv4.y), dup2f(zv4.z), dup2f(zv4.w)};
                ulonglong2 wa = *(const ulonglong2*)(w2 + c * 256 + ob2);
                ulonglong2 wb = *(const ulonglong2*)(w2 + c * 256 + ob2 + 4);
                u64 wp[4] = {wa.x, wa.y, wb.x, wb.y};
#pragma unroll
                for (int op = 0; op < 4; ++op)
#pragma unroll
                    for (int ti = 0; ti < 4; ++ti) fma2(acc[op][ti], wp[op], zv[ti]);
            }
#pragma unroll
            for (int op = 0; op < 4; ++op) {
                float lo[4], hi[4];
#pragma unroll
                for (int ti = 0; ti < 4; ++ti) upk(lo[ti], hi[ti], acc[op][ti]);
                float4 v0 = {lo[0], lo[1], lo[2], lo[3]};
                float4 v1 = {hi[0], hi[1], hi[2], hi[3]};
                *(float4*)&ob_out[(ob2 + 2 * op) * TLEN + t0 + tb] = v0;
                *(float4*)&ob_out[(ob2 + 2 * op + 1) * TLEN + t0 + tb] = v1;
            }
        }
    }
}

/* --------------------------------------------------------------- */
extern "C" void kernel_launch(void* const* d_in, const int* in_sizes, int n_in,
                              void* d_out, int out_size) {
    const float* x        = (const float*)d_in[0];
    const float* c        = (const float*)d_in[1];
    const float* first_w  = (const float*)d_in[2];
    const float* first_b  = (const float*)d_in[3];
    const float* conv_w   = (const float*)d_in[4];
    const float* conv_b   = (const float*)d_in[5];
    const float* cond_w   = (const float*)d_in[6];
    const float* out_w    = (const float*)d_in[7];
    const float* out_b    = (const float*)d_in[8];
    const float* skip_w   = (const float*)d_in[9];
    const float* skip_b   = (const float*)d_in[10];
    const float* last1_w  = (const float*)d_in[11];
    const float* last1_b  = (const float*)d_in[12];
    const float* last2_w  = (const float*)d_in[13];
    const float* last2_b  = (const float*)d_in[14];
    const float* conv_in_w= (const float*)d_in[15];
    const float* up_w0    = (const float*)d_in[16];
    const float* up_w1    = (const float*)d_in[17];
    float* out = (float*)d_out;

    int dev = 0;
    cudaGetDevice(&dev);
    int sms = 148;
    cudaDeviceGetAttribute(&sms, cudaDevAttrMultiProcessorCount, dev);

    cudaFuncSetAttribute(first_kernel, cudaFuncAttributeMaxDynamicSharedMemorySize, 131072);
    cudaFuncSetAttribute(layer_kernel, cudaFuncAttributeMaxDynamicSharedMemorySize, SM_TOTAL);
    cudaFuncSetAttribute(last_kernel,  cudaFuncAttributeMaxDynamicSharedMemorySize, 114688);

    {
        int total = NPG + NPZ + NPF;
        prep_all_kernel<<<(total + 255) / 256, 256>>>(
            conv_w, cond_w, skip_w, out_w, first_w, last1_w, last2_w);
    }
    cond_all_kernel<<<B_SZ * CCH, 256>>>(c, conv_in_w, up_w0, up_w1);
    first_kernel<<<sms, 256, 131072>>>(x, first_b);
    for (int l = 0; l < LAYERS; ++l) {
        int d = 1 << (l % 10);
        layer_kernel<<<sms, 256, SM_TOTAL>>>(l, d, l & 1, l == 0 ? 1 : 0,
                                             conv_b, skip_b, out_b);
    }
    last_kernel<<<sms, 256, 114688>>>(last1_b, last2_b, out);
}

// round 16
// speedup vs baseline: 1.1949x; 1.1201x over previous
#include <cuda_runtime.h>
#include <cuda_fp16.h>
#include <math.h>
#include <stdint.h>

#define LAYERS 30
#define B_SZ 4
#define TLEN 32000
#define TT 64
#define NTILES (B_SZ * (TLEN / TT))
#define LTT 64
#define LNT (B_SZ * (TLEN / LTT))   /* 2000 */
#define CH 64
#define CCH 80

/* layer SMEM: double B1, double B2, double epilogue staging */
#define STR 144
#define SM_BUF 59904              /* one B1 buffer: hi 29952 + mid 29952 */
#define SM_B1M_OFF 29952
#define SM_B2 119808              /* + q*18432 ; mid at +9216 */
#define SM_EPI 156672             /* + e*35840 ; SK at +0, HH +17408, HM +26624 */
#define EPI_STRIDE 35840
#define EPI_HH_OFF 17408
#define EPI_HM_OFF 26624
#define SM_TOTAL 228352

typedef unsigned long long u64;
typedef uint32_t u32;
typedef unsigned short u16;

__device__ __half g_hh[2][B_SZ * CH * TLEN];
__device__ __half g_hm[2][B_SZ * CH * TLEN];
__device__ float g_skips[B_SZ * CH * TLEN];
__device__ __half g_cbh[B_SZ * CCH * TLEN];
__device__ __half g_cbm[B_SZ * CCH * TLEN];
__device__ u32 g_gwh[LAYERS * 128 * 104];   /* fp16 pair weights, hi plane only */
__device__ u32 g_wzh[LAYERS * 128 * 32];
__device__ float g_wfirstT[256 * 64];
__device__ float g_wl1T[64 * 64];
__device__ float g_wl2T[64 * 256];

__device__ __forceinline__ u32 pkhf(float a, float b) {
    __half2 h = __floats2half2_rn(a, b);
    return *reinterpret_cast<u32*>(&h);
}
__device__ __forceinline__ float hflo(float a) { return __half2float(__float2half_rn(a)); }
__device__ __forceinline__ float2 uph2(u32 v) {
    __half2 h = *reinterpret_cast<__half2*>(&v);
    return make_float2(__half2float(h.x), __half2float(h.y));
}
/* gated activation tanh(a)*sigmoid(b), 3 MUFU; clamps keep product < 2^87 */
__device__ __forceinline__ float gact(float a, float b) {
    a = fmaxf(a, -15.f);
    b = fmaxf(b, -30.f);
    float e1 = __expf(-2.f * a);
    float e2 = __expf(-b);
    return (1.f - e1) * __fdividef(1.f, (1.f + e1) * (1.f + e2));
}

__device__ __forceinline__ u32 smem_u32(const void* p) {
    u32 a;
    asm("{ .reg .u64 t; cvta.to.shared.u64 t, %1; cvt.u32.u64 %0, t; }" : "=r"(a) : "l"(p));
    return a;
}
__device__ __forceinline__ void mma16816(float* d, const u32* a, const u32* b) {
    asm volatile("mma.sync.aligned.m16n8k16.row.col.f32.f16.f16.f32 "
        "{%0,%1,%2,%3}, {%4,%5,%6,%7}, {%8,%9}, {%0,%1,%2,%3};"
        : "+f"(d[0]), "+f"(d[1]), "+f"(d[2]), "+f"(d[3])
        : "r"(a[0]), "r"(a[1]), "r"(a[2]), "r"(a[3]), "r"(b[0]), "r"(b[1]));
}
__device__ __forceinline__ void ldmT_x4(u32* r, u32 addr) {
    asm volatile("ldmatrix.sync.aligned.m8n8.x4.trans.shared.b16 {%0,%1,%2,%3}, [%4];"
        : "=r"(r[0]), "=r"(r[1]), "=r"(r[2]), "=r"(r[3]) : "r"(addr));
}
__device__ __forceinline__ void ldmT_x2(u32* r, u32 addr) {
    asm volatile("ldmatrix.sync.aligned.m8n8.x2.trans.shared.b16 {%0,%1}, [%2];"
        : "=r"(r[0]), "=r"(r[1]) : "r"(addr));
}
#define CP16(dst, src) asm volatile("cp.async.cg.shared.global [%0], [%1], 16;" \
    :: "r"((u32)(dst)), "l"(src) : "memory")
#define CP8(dst, src)  asm volatile("cp.async.ca.shared.global [%0], [%1], 8;" \
    :: "r"((u32)(dst)), "l"(src) : "memory")
#define CP4(dst, src)  asm volatile("cp.async.ca.shared.global [%0], [%1], 4;" \
    :: "r"((u32)(dst)), "l"(src) : "memory")
#define CP_COMMIT() asm volatile("cp.async.commit_group;" ::: "memory")
#define CP_WAIT0()  asm volatile("cp.async.wait_group 0;" ::: "memory")
#define STS32(a, v) asm volatile("st.shared.b32 [%0], %1;" :: "r"((u32)(a)), "r"((u32)(v)) : "memory")

__device__ __forceinline__ u64 pk2(float lo, float hi) {
    u64 r; asm("mov.b64 %0, {%1, %2};" : "=l"(r) : "f"(lo), "f"(hi)); return r;
}
__device__ __forceinline__ u64 dup2f(float v) { return pk2(v, v); }
__device__ __forceinline__ void fma2(u64& d, u64 a, u64 b) {
    asm("fma.rn.f32x2 %0, %1, %2, %0;" : "+l"(d) : "l"(a), "l"(b));
}
__device__ __forceinline__ void upk(float& lo, float& hi, u64 v) {
    asm("mov.b64 {%0, %1}, %2;" : "=f"(lo), "=f"(hi) : "l"(v));
}

__device__ __forceinline__ int orig_gate_row(int r) {
    int q = r >> 4, i = r & 15;
    return (i < 8) ? (8 * q + i) : (64 + 8 * q + (i - 8));
}

/* ---------------- merged weight prep ---------------- */
#define NPG (LAYERS * 128 * 104)
#define NPZ (LAYERS * 128 * 32)
#define NPF (16384 + 4096 + 16384)
__global__ void prep_all_kernel(const float* __restrict__ conv_w,
                                const float* __restrict__ cond_w,
                                const float* __restrict__ skip_w,
                                const float* __restrict__ out_w,
                                const float* __restrict__ first_w,
                                const float* __restrict__ last1_w,
                                const float* __restrict__ last2_w) {
    int idx = blockIdx.x * blockDim.x + threadIdx.x;
    if (idx < NPG) {
        int l = idx / (128 * 104), rem = idx % (128 * 104);
        int r = rem / 104, kp = rem % 104;
        int o = orig_gate_row(r);
        float w[2];
#pragma unroll
        for (int e = 0; e < 2; ++e) {
            int k = 2 * kp + e;
            if (k < 64)       w[e] = conv_w[((l * 128 + o) * 64 + k) * 2 + 0];
            else if (k < 128) w[e] = conv_w[((l * 128 + o) * 64 + (k - 64)) * 2 + 1];
            else              w[e] = cond_w[(l * 128 + o) * 80 + (k - 128)];
        }
        g_gwh[idx] = pkhf(w[0], w[1]);
    } else if (idx < NPG + NPZ) {
        int j = idx - NPG;
        int l = j / (128 * 32), rem = j % (128 * 32);
        int r = rem / 32, kp = rem % 32;
        float w[2];
#pragma unroll
        for (int e = 0; e < 2; ++e) {
            int k = 2 * kp + e;
            w[e] = (r < 64) ? skip_w[(l * 64 + r) * 64 + k]
                            : out_w[(l * 64 + (r - 64)) * 64 + k];
        }
        g_wzh[j] = pkhf(w[0], w[1]);
    } else if (idx < NPG + NPZ + NPF) {
        int j = idx - NPG - NPZ;
        if (j < 16384) {
            int c = j >> 6, o = j & 63;
            g_wfirstT[j] = first_w[o * 256 + c];
        } else if (j < 16384 + 4096) {
            int jj = j - 16384; int c = jj >> 6, o = jj & 63;
            g_wl1T[jj] = last1_w[o * 64 + c];
        } else {
            int jj = j - 16384 - 4096; int c = jj >> 8, o = jj & 255;
            g_wl2T[jj] = last2_w[o * 64 + c];
        }
    }
}

/* ---------------- merged conditioning ---------------- */
__global__ void __launch_bounds__(256) cond_all_kernel(
        const float* __restrict__ cin, const float* __restrict__ conv_in_w,
        const float* __restrict__ w0, const float* __restrict__ w1) {
    __shared__ float c1row[400];
    __shared__ float c2row[4000];
    int blk = blockIdx.x;
    int b = blk / CCH, o = blk % CCH;
    int tid = threadIdx.x;
    for (int f = tid; f < 400; f += 256) {
        const float* src = cin + (size_t)(b * CCH) * 400 + f;
        float acc = 0.f;
#pragma unroll 8
        for (int ch = 0; ch < 80; ++ch)
            acc += __ldg(&conv_in_w[o * 80 + ch]) * __ldg(&src[ch * 400]);
        c1row[f] = acc;
    }
    __syncthreads();
    for (int t = tid; t < 4000; t += 256) {
        float acc = 0.f;
        int base = t - 10;
        for (int j = 0; j < 21; ++j) {
            int u = base + j;
            if (u >= 0 && u < 4000) acc += __ldg(&w0[j]) * c1row[u / 10];
        }
        c2row[t] = acc;
    }
    __syncthreads();
    size_t rowoff = (size_t)(b * CCH + o) * TLEN;
    for (int t = tid; t < TLEN; t += 256) {
        float acc = 0.f;
        int base = t - 8;
        for (int j = 0; j < 17; ++j) {
            int u = base + j;
            if (u >= 0 && u < TLEN) acc += __ldg(&w1[j]) * c2row[u / 8];
        }
        g_cbh[rowoff + t] = __float2half_rn(acc);
        g_cbm[rowoff + t] = __float2half_rn(acc - hflo(acc));
    }
}

/* ---------------- first 1x1 conv (FFMA2) -> fp16 hi/mid planes ------------- */
__global__ void __launch_bounds__(256) first_kernel(const float* __restrict__ x,
                                                    const float* __restrict__ first_b) {
    extern __shared__ float sm[];
    float* xs = sm;
    float* wf = sm + 16384;
    for (int i = threadIdx.x; i < 16384 / 4; i += blockDim.x)
        ((float4*)wf)[i] = ((const float4*)g_wfirstT)[i];
    int to = threadIdx.x & 15, oo = threadIdx.x >> 4;
    int tb = to * 4, ob = oo * 4;
    for (int tile = blockIdx.x; tile < NTILES; tile += gridDim.x) {
        int b = tile / (TLEN / TT), t0 = (tile % (TLEN / TT)) * TT;
        __syncthreads();
        const float* xb = x + (size_t)b * 256 * TLEN;
        for (int i = threadIdx.x; i < 256 * (TT / 4); i += blockDim.x) {
            int c = i / (TT / 4), q = i % (TT / 4);
            ((float4*)xs)[c * (TT / 4) + q] = *(const float4*)&xb[c * TLEN + t0 + q * 4];
        }
        __syncthreads();
        u64 acc[2][4];
#pragma unroll
        for (int op = 0; op < 2; ++op) {
            u64 bv = pk2(first_b[ob + 2 * op], first_b[ob + 2 * op + 1]);
#pragma unroll
            for (int ti = 0; ti < 4; ++ti) acc[op][ti] = bv;
        }
#pragma unroll 2
        for (int c = 0; c < 256; ++c) {
            float4 xv4 = *(const float4*)(xs + c * TT + tb);
            u64 xv[4] = {dup2f(xv4.x), dup2f(xv4.y), dup2f(xv4.z), dup2f(xv4.w)};
            ulonglong2 wv = *(const ulonglong2*)(wf + c * 64 + ob);
            u64 w2[2] = {wv.x, wv.y};
#pragma unroll
            for (int op = 0; op < 2; ++op)
#pragma unroll
                for (int ti = 0; ti < 4; ++ti) fma2(acc[op][ti], w2[op], xv[ti]);
        }
        __half* hh = g_hh[0] + (size_t)b * CH * TLEN;
        __half* hm = g_hm[0] + (size_t)b * CH * TLEN;
#pragma unroll
        for (int op = 0; op < 2; ++op) {
            float lo[4], hi[4];
#pragma unroll
            for (int ti = 0; ti < 4; ++ti) upk(lo[ti], hi[ti], acc[op][ti]);
            int r0 = ob + 2 * op, r1 = r0 + 1;
            u32* p;
            p = (u32*)(hh + (size_t)r0 * TLEN + t0 + tb);
            p[0] = pkhf(lo[0], lo[1]); p[1] = pkhf(lo[2], lo[3]);
            p = (u32*)(hm + (size_t)r0 * TLEN + t0 + tb);
            p[0] = pkhf(lo[0] - hflo(lo[0]), lo[1] - hflo(lo[1]));
            p[1] = pkhf(lo[2] - hflo(lo[2]), lo[3] - hflo(lo[3]));
            p = (u32*)(hh + (size_t)r1 * TLEN + t0 + tb);
            p[0] = pkhf(hi[0], hi[1]); p[1] = pkhf(hi[2], hi[3]);
            p = (u32*)(hm + (size_t)r1 * TLEN + t0 + tb);
            p[0] = pkhf(hi[0] - hflo(hi[0]), hi[1] - hflo(hi[1]));
            p[1] = pkhf(hi[2] - hflo(hi[2]), hi[3] - hflo(hi[3]));
        }
    }
}

/* ---- async B1 issue ---- */
__device__ __forceinline__ void issue_b1(char* smc, u32 sb, u32 bufoff, int tile,
                                         int d, const __half* phh,
                                         const __half* phm, int tid) {
    int b = tile / (TLEN / LTT), t0 = (tile % (TLEN / LTT)) * LTT;
    const __half* hbh = phh + (size_t)b * CH * TLEN;
    const __half* hbm = phm + (size_t)b * CH * TLEN;
    u32 dsth = sb + bufoff;
    u32 dstm = dsth + SM_B1M_OFF;
    for (int i = tid; i < 144 * 8; i += 256) {
        int r = i >> 3, g = i & 7;
        const __half *s1, *s2;
        if (r < 64) {
            size_t a = (size_t)r * TLEN + t0 + g * 8;
            s1 = hbh + a; s2 = hbm + a;
        } else {
            size_t a = ((size_t)(b * CCH + r - 64)) * TLEN + t0 + g * 8;
            s1 = g_cbh + a; s2 = g_cbm + a;
        }
        u32 off = (u32)((64 + r) * STR + g * 16);
        CP16(dsth + off, s1);
        CP16(dstm + off, s2);
    }
    for (int i = tid; i < 64 * 8; i += 256) {
        int r = i >> 3, g = i & 7;
        int tg = t0 - d + g * 8;
        const __half* sh = hbh + (size_t)r * TLEN;
        const __half* sm2 = hbm + (size_t)r * TLEN;
        u32 off = (u32)(r * STR + g * 16);
        if (tg >= 0 && d >= 8) {
            CP16(dsth + off, sh + tg);
            CP16(dstm + off, sm2 + tg);
        } else if (tg >= 0 && d == 4) {
            CP8(dsth + off, sh + tg);      CP8(dsth + off + 8, sh + tg + 4);
            CP8(dstm + off, sm2 + tg);     CP8(dstm + off + 8, sm2 + tg + 4);
        } else if (tg >= 0 && d == 2) {
#pragma unroll
            for (int q = 0; q < 4; ++q) {
                CP4(dsth + off + q * 4, sh + tg + q * 2);
                CP4(dstm + off + q * 4, sm2 + tg + q * 2);
            }
        } else {
#pragma unroll
            for (int e = 0; e < 4; ++e) {
                int tt0 = tg + 2 * e, tt1 = tt0 + 1;
                u16 h0 = (tt0 >= 0) ? *(const u16*)(sh + tt0) : 0;
                u16 h1 = (tt1 >= 0) ? *(const u16*)(sh + tt1) : 0;
                u16 m0 = (tt0 >= 0) ? *(const u16*)(sm2 + tt0) : 0;
                u16 m1 = (tt1 >= 0) ? *(const u16*)(sm2 + tt1) : 0;
                STS32(dsth + off + e * 4, (u32)h0 | ((u32)h1 << 16));
                STS32(dstm + off + e * 4, (u32)m0 | ((u32)m1 << 16));
            }
        }
    }
}

/* ---- async epilogue staging into buffer eb ---- */
__device__ __forceinline__ void issue_epi(u32 sb, int eb, int tile,
                                          const __half* phh,
                                          const __half* phm, int tid) {
    int b = tile / (TLEN / LTT), t0 = (tile % (TLEN / LTT)) * LTT;
    const float* skb = g_skips + (size_t)b * CH * TLEN;
    const __half* hbh = phh + (size_t)b * CH * TLEN;
    const __half* hbm = phm + (size_t)b * CH * TLEN;
    u32 base = sb + SM_EPI + (u32)eb * EPI_STRIDE;
    for (int i = tid; i < 1024; i += 256) {
        int r = i >> 4, g = i & 15;
        CP16(base + r * 272 + g * 16, skb + (size_t)r * TLEN + t0 + g * 4);
    }
    for (int i = tid; i < 512; i += 256) {
        int r = i >> 3, g = i & 7;
        CP16(base + EPI_HH_OFF + r * 144 + g * 16, hbh + (size_t)r * TLEN + t0 + g * 8);
        CP16(base + EPI_HM_OFF + r * 144 + g * 16, hbm + (size_t)r * TLEN + t0 + g * 8);
    }
}

/* ---------------- fused residual layer: fp16 2-term, pipelined ------------- */
__global__ void __launch_bounds__(256, 1) layer_kernel(int l, int d, int hin, int first_layer,
        const float* __restrict__ conv_b, const float* __restrict__ skip_b,
        const float* __restrict__ out_b) {
    extern __shared__ char smc[];
    u32 sb = smem_u32(smc);
    int tid = threadIdx.x, w = tid >> 5, lane = tid & 31;
    int lq = lane >> 2, lr = lane & 3;

    u32 Ah[13][4], Zh[4][4];
    {
        const u32* gh = g_gwh + ((size_t)l * 128 + 16 * w) * 104;
#pragma unroll
        for (int ks = 0; ks < 13; ++ks) {
            int kp = 8 * ks + lr;
            Ah[ks][0] = gh[lq * 104 + kp];     Ah[ks][1] = gh[(8 + lq) * 104 + kp];
            Ah[ks][2] = gh[lq * 104 + kp + 4]; Ah[ks][3] = gh[(8 + lq) * 104 + kp + 4];
        }
        const u32* zh = g_wzh + ((size_t)l * 128 + 16 * w) * 32;
#pragma unroll
        for (int ks = 0; ks < 4; ++ks) {
            int kp = 8 * ks + lr;
            Zh[ks][0] = zh[lq * 32 + kp];     Zh[ks][1] = zh[(8 + lq) * 32 + kp];
            Zh[ks][2] = zh[lq * 32 + kp + 4]; Zh[ks][3] = zh[(8 + lq) * 32 + kp + 4];
        }
    }
    int gch = 8 * w + lq;
    float ba = conv_b[l * 128 + gch];
    float bb = conv_b[l * 128 + 64 + gch];
    int r1 = 16 * w + lq;
    float bs0 = (r1 < 64) ? skip_b[l * 64 + r1] : out_b[l * 64 + r1 - 64];
    float bs1 = (r1 < 64) ? skip_b[l * 64 + r1 + 8] : out_b[l * 64 + r1 - 56];

    const __half* phh = g_hh[hin];
    const __half* phm = g_hm[hin];
    __half* qhh = g_hh[hin ^ 1];
    __half* qhm = g_hm[hin ^ 1];

    int tile = blockIdx.x;
    if (tile >= LNT) return;

    issue_b1(smc, sb, 0, tile, d, phh, phm, tid);
    CP_COMMIT();
    CP_WAIT0();
    __syncthreads();

    int nt = tile + gridDim.x;
    if (nt < LNT)
        issue_b1(smc, sb, SM_BUF, nt, d, phh, phm, tid);
    issue_epi(sb, 0, tile, phh, phm, tid);
    CP_COMMIT();

    /* peel: gate(T0) from buf0 -> B2[0] */
    {
        u32 bufH = sb;
        u32 bufM = bufH + SM_B1M_OFF;
        u32 b1h_l4 = bufH + lane * STR;
        u32 b1m_l4 = bufM + lane * STR;
        u32 b1h_l2 = bufH + (lane & 15) * STR + 192 * STR;
        u32 b1m_l2 = bufM + (lane & 15) * STR + 192 * STR;
        int wb2h_off = SM_B2, wb2m_off = SM_B2 + 9216;
#pragma unroll 1
        for (int j = 0; j < 8; ++j) {
            float D0[4] = {0, 0, 0, 0}, D1[4] = {0, 0, 0, 0};
            int ta = j * 16;
#pragma unroll
            for (int kk = 0; kk < 6; ++kk) {
                u32 bh[4], bm[4];
                ldmT_x4(bh, b1h_l4 + kk * 32 * STR + ta);
                ldmT_x4(bm, b1m_l4 + kk * 32 * STR + ta);
                mma16816(D0, Ah[2 * kk], bh);
                mma16816(D1, Ah[2 * kk], bm);
                mma16816(D0, Ah[2 * kk + 1], bh + 2);
                mma16816(D1, Ah[2 * kk + 1], bm + 2);
            }
            {
                u32 bh[2], bm[2];
                ldmT_x2(bh, b1h_l2 + ta);
                ldmT_x2(bm, b1m_l2 + ta);
                mma16816(D0, Ah[12], bh);
                mma16816(D1, Ah[12], bm);
            }
            float a0 = D0[0] + D1[0] + ba;
            float a1 = D0[1] + D1[1] + ba;
            float g0 = D0[2] + D1[2] + bb;
            float g1 = D0[3] + D1[3] + bb;
            float z0 = gact(a0, g0), z1 = gact(a1, g1);
            int zoff = gch * STR + (j * 8 + lr * 2) * 2;
            *(u32*)(smc + wb2h_off + zoff) = pkhf(z0, z1);
            *(u32*)(smc + wb2m_off + zoff) = pkhf(z0 - hflo(z0), z1 - hflo(z1));
        }
    }

    int gbuf = 1, zb = 0, eb = 0;

    /* ---- main loop: skip(tile) + gate(nt), one sync per tile ---- */
    while (nt < LNT) {
        CP_WAIT0();
        __syncthreads();

        int nnt = nt + gridDim.x;
        if (nnt < LNT)
            issue_b1(smc, sb, (u32)((gbuf ^ 1) * SM_BUF), nnt, d, phh, phm, tid);
        issue_epi(sb, eb ^ 1, nt, phh, phm, tid);
        CP_COMMIT();

        int b_s = tile / (TLEN / LTT), t0_s = (tile % (TLEN / LTT)) * LTT;
        u32 rb2h = sb + SM_B2 + zb * 18432;
        u32 rb2m = rb2h + 9216;
        u32 b2h_l4 = rb2h + lane * STR;
        u32 b2m_l4 = rb2m + lane * STR;
        int wb2h_off = SM_B2 + (zb ^ 1) * 18432;
        int wb2m_off = wb2h_off + 9216;
        u32 bufH = sb + gbuf * SM_BUF;
        u32 bufM = bufH + SM_B1M_OFF;
        u32 b1h_l4 = bufH + lane * STR;
        u32 b1m_l4 = bufM + lane * STR;
        u32 b1h_l2 = bufH + (lane & 15) * STR + 192 * STR;
        u32 b1m_l2 = bufM + (lane & 15) * STR + 192 * STR;
        u32 epiB = sb + SM_EPI + (u32)eb * EPI_STRIDE;
        float* skb = g_skips + (size_t)b_s * CH * TLEN;

#pragma unroll 1
        for (int j = 0; j < 8; ++j) {
            int ta = j * 16;
            float E0[4] = {0, 0, 0, 0}, E1[4] = {0, 0, 0, 0};
            {
                u32 sh0[4], sm0[4], sh1[4], sm1[4];
                ldmT_x4(sh0, b2h_l4 + ta);
                ldmT_x4(sm0, b2m_l4 + ta);
                ldmT_x4(sh1, b2h_l4 + 32 * STR + ta);
                ldmT_x4(sm1, b2m_l4 + 32 * STR + ta);
                mma16816(E0, Zh[0], sh0);
                mma16816(E1, Zh[0], sm0);
                mma16816(E0, Zh[1], sh0 + 2);
                mma16816(E1, Zh[1], sm0 + 2);
                mma16816(E0, Zh[2], sh1);
                mma16816(E1, Zh[2], sm1);
                mma16816(E0, Zh[3], sh1 + 2);
                mma16816(E1, Zh[3], sm1 + 2);
            }
            float D0[4] = {0, 0, 0, 0}, D1[4] = {0, 0, 0, 0};
#pragma unroll
            for (int kk = 0; kk < 6; ++kk) {
                u32 bh[4], bm[4];
                ldmT_x4(bh, b1h_l4 + kk * 32 * STR + ta);
                ldmT_x4(bm, b1m_l4 + kk * 32 * STR + ta);
                mma16816(D0, Ah[2 * kk], bh);
                mma16816(D1, Ah[2 * kk], bm);
                mma16816(D0, Ah[2 * kk + 1], bh + 2);
                mma16816(D1, Ah[2 * kk + 1], bm + 2);
            }
            {
                u32 bh[2], bm[2];
                ldmT_x2(bh, b1h_l2 + ta);
                ldmT_x2(bm, b1m_l2 + ta);
                mma16816(D0, Ah[12], bh);
                mma16816(D1, Ah[12], bm);
            }
            float a0 = D0[0] + D1[0] + ba;
            float a1 = D0[1] + D1[1] + ba;
            float g0 = D0[2] + D1[2] + bb;
            float g1 = D0[3] + D1[3] + bb;
            float z0 = gact(a0, g0), z1 = gact(a1, g1);
            int zoff = gch * STR + (j * 8 + lr * 2) * 2;
            *(u32*)(smc + wb2h_off + zoff) = pkhf(z0, z1);
            *(u32*)(smc + wb2m_off + zoff) = pkhf(z0 - hflo(z0), z1 - hflo(z1));
            float e0 = E0[0] + E1[0] + bs0;
            float e1 = E0[1] + E1[1] + bs0;
            float e2 = E0[2] + E1[2] + bs1;
            float e3 = E0[3] + E1[3] + bs1;
            int tl = j * 8 + lr * 2;
            int t = t0_s + tl;
            if (r1 < 64) {
                float2 v0 = {e0, e1}, v1 = {e2, e3};
                if (!first_layer) {
                    float2 o0 = *(const float2*)(smc + (epiB - sb) + r1 * 272 + tl * 4);
                    float2 o1 = *(const float2*)(smc + (epiB - sb) + (r1 + 8) * 272 + tl * 4);
                    v0.x += o0.x; v0.y += o0.y; v1.x += o1.x; v1.y += o1.y;
                }
                *(float2*)(skb + (size_t)r1 * TLEN + t) = v0;
                *(float2*)(skb + (size_t)(r1 + 8) * TLEN + t) = v1;
            } else {
                int c0 = r1 - 64, c1 = c0 + 8;
                const char* eB = smc + (epiB - sb);
                float2 i0h = uph2(*(const u32*)(eB + EPI_HH_OFF + c0 * 144 + tl * 2));
                float2 i0m = uph2(*(const u32*)(eB + EPI_HM_OFF + c0 * 144 + tl * 2));
                float2 i1h = uph2(*(const u32*)(eB + EPI_HH_OFF + c1 * 144 + tl * 2));
                float2 i1m = uph2(*(const u32*)(eB + EPI_HM_OFF + c1 * 144 + tl * 2));
                float v0 = e0 + i0h.x + i0m.x;
                float v1 = e1 + i0h.y + i0m.y;
                float v2 = e2 + i1h.x + i1m.x;
                float v3 = e3 + i1h.y + i1m.y;
                size_t a0i = (size_t)b_s * CH * TLEN + (size_t)c0 * TLEN + t;
                size_t a1i = (size_t)b_s * CH * TLEN + (size_t)c1 * TLEN + t;
                *(u32*)(qhh + a0i) = pkhf(v0, v1);
                *(u32*)(qhm + a0i) = pkhf(v0 - hflo(v0), v1 - hflo(v1));
                *(u32*)(qhh + a1i) = pkhf(v2, v3);
                *(u32*)(qhm + a1i) = pkhf(v2 - hflo(v2), v3 - hflo(v3));
            }
        }
        tile = nt; nt = nnt; gbuf ^= 1; zb ^= 1; eb ^= 1;
    }

    /* ---- final: skip(tile) with B2[zb], epi[eb] ---- */
    CP_WAIT0();
    __syncthreads();
    {
        int b_s = tile / (TLEN / LTT), t0_s = (tile % (TLEN / LTT)) * LTT;
        u32 rb2h = sb + SM_B2 + zb * 18432;
        u32 rb2m = rb2h + 9216;
        u32 b2h_l4 = rb2h + lane * STR;
        u32 b2m_l4 = rb2m + lane * STR;
        const char* eB = smc + SM_EPI + eb * EPI_STRIDE;
        float* skb = g_skips + (size_t)b_s * CH * TLEN;
#pragma unroll 1
        for (int j = 0; j < 8; ++j) {
            float E0[4] = {0, 0, 0, 0}, E1[4] = {0, 0, 0, 0};
            int ta = j * 16;
#pragma unroll
            for (int kk = 0; kk < 2; ++kk) {
                u32 bh[4], bm[4];
                ldmT_x4(bh, b2h_l4 + kk * 32 * STR + ta);
                ldmT_x4(bm, b2m_l4 + kk * 32 * STR + ta);
                mma16816(E0, Zh[2 * kk], bh);
                mma16816(E1, Zh[2 * kk], bm);
                mma16816(E0, Zh[2 * kk + 1], bh + 2);
                mma16816(E1, Zh[2 * kk + 1], bm + 2);
            }
            float e0 = E0[0] + E1[0] + bs0;
            float e1 = E0[1] + E1[1] + bs0;
            float e2 = E0[2] + E1[2] + bs1;
            float e3 = E0[3] + E1[3] + bs1;
            int tl = j * 8 + lr * 2;
            int t = t0_s + tl;
            if (r1 < 64) {
                float2 v0 = {e0, e1}, v1 = {e2, e3};
                if (!first_layer) {
                    float2 o0 = *(const float2*)(eB + r1 * 272 + tl * 4);
                    float2 o1 = *(const float2*)(eB + (r1 + 8) * 272 + tl * 4);
                    v0.x += o0.x; v0.y += o0.y; v1.x += o1.x; v1.y += o1.y;
                }
                *(float2*)(skb + (size_t)r1 * TLEN + t) = v0;
                *(float2*)(skb + (size_t)(r1 + 8) * TLEN + t) = v1;
            } else {
                int c0 = r1 - 64, c1 = c0 + 8;
                float2 i0h = uph2(*(const u32*)(eB + EPI_HH_OFF + c0 * 144 + tl * 2));
                float2 i0m = uph2(*(const u32*)(eB + EPI_HM_OFF + c0 * 144 + tl * 2));
                float2 i1h = uph2(*(const u32*)(eB + EPI_HH_OFF + c1 * 144 + tl * 2));
                float2 i1m = uph2(*(const u32*)(eB + EPI_HM_OFF + c1 * 144 + tl * 2));
                float v0 = e0 + i0h.x + i0m.x;
                float v1 = e1 + i0h.y + i0m.y;
                float v2 = e2 + i1h.x + i1m.x;
                float v3 = e3 + i1h.y + i1m.y;
                size_t a0i = (size_t)b_s * CH * TLEN + (size_t)c0 * TLEN + t;
                size_t a1i = (size_t)b_s * CH * TLEN + (size_t)c1 * TLEN + t;
                *(u32*)(qhh + a0i) = pkhf(v0, v1);
                *(u32*)(qhm + a0i) = pkhf(v0 - hflo(v0), v1 - hflo(v1));
                *(u32*)(qhh + a1i) = pkhf(v2, v3);
                *(u32*)(qhm + a1i) = pkhf(v2 - hflo(v2), v3 - hflo(v3));
            }
        }
    }
}

/* ---------------- last: relu,1x1,relu,1x1 (FFMA2) ---------------- */
__global__ void __launch_bounds__(256) last_kernel(const float* __restrict__ l1b,
                                                   const float* __restrict__ l2b,
                                                   float* __restrict__ out) {
    extern __shared__ float sm[];
    float* w1 = sm;
    float* w2 = sm + 4096;
    float* sk = sm + 20480;
    float* o1 = sm + 24576;
    for (int i = threadIdx.x; i < 4096 / 4; i += blockDim.x)
        ((float4*)w1)[i] = ((const float4*)g_wl1T)[i];
    for (int i = threadIdx.x; i < 16384 / 4; i += blockDim.x)
        ((float4*)w2)[i] = ((const float4*)g_wl2T)[i];
    int to = threadIdx.x & 15, oo = threadIdx.x >> 4;
    int tb = to * 4;
    for (int tile = blockIdx.x; tile < NTILES; tile += gridDim.x) {
        int b = tile / (TLEN / TT), t0 = (tile % (TLEN / TT)) * TT;
        __syncthreads();
        const float* skb = g_skips + (size_t)b * CH * TLEN;
        for (int i = threadIdx.x; i < CH * (TT / 4); i += blockDim.x) {
            int c = i / (TT / 4), q = i % (TT / 4);
            float4 v = *(const float4*)&skb[c * TLEN + t0 + q * 4];
            v.x = fmaxf(v.x, 0.f); v.y = fmaxf(v.y, 0.f);
            v.z = fmaxf(v.z, 0.f); v.w = fmaxf(v.w, 0.f);
            ((float4*)sk)[c * (TT / 4) + q] = v;
        }
        __syncthreads();
        {
            int ob = oo * 4;
            u64 acc[2][4];
#pragma unroll
            for (int op = 0; op < 2; ++op) {
                u64 bv = pk2(l1b[ob + 2 * op], l1b[ob + 2 * op + 1]);
#pragma unroll
                for (int ti = 0; ti < 4; ++ti) acc[op][ti] = bv;
            }
#pragma unroll 2
            for (int c = 0; c < 64; ++c) {
                float4 xv4 = *(const float4*)(sk + c * TT + tb);
                u64 xv[4] = {dup2f(xv4.x), dup2f(xv4.y), dup2f(xv4.z), dup2f(xv4.w)};
                ulonglong2 wv = *(const ulonglong2*)(w1 + c * 64 + ob);
                u64 wp[2] = {wv.x, wv.y};
#pragma unroll
                for (int op = 0; op < 2; ++op)
#pragma unroll
                    for (int ti = 0; ti < 4; ++ti) fma2(acc[op][ti], wp[op], xv[ti]);
            }
#pragma unroll
            for (int op = 0; op < 2; ++op) {
                float lo[4], hi[4];
#pragma unroll
                for (int ti = 0; ti < 4; ++ti) upk(lo[ti], hi[ti], acc[op][ti]);
                float4 v0 = {fmaxf(lo[0], 0.f), fmaxf(lo[1], 0.f), fmaxf(lo[2], 0.f), fmaxf(lo[3], 0.f)};
                float4 v1 = {fmaxf(hi[0], 0.f), fmaxf(hi[1], 0.f), fmaxf(hi[2], 0.f), fmaxf(hi[3], 0.f)};
                *(float4*)(o1 + (ob + 2 * op) * TT + tb) = v0;
                *(float4*)(o1 + (ob + 2 * op + 1) * TT + tb) = v1;
            }
        }
        __syncthreads();
        float* ob_out = out + (size_t)b * 256 * TLEN;
#pragma unroll
        for (int half = 0; half < 2; ++half) {
            int ob2 = half * 128 + oo * 8;
            u64 acc[4][4];
#pragma unroll
            for (int op = 0; op < 4; ++op) {
                u64 bv = pk2(l2b[ob2 + 2 * op], l2b[ob2 + 2 * op + 1]);
#pragma unroll
                for (int ti = 0; ti < 4; ++ti) acc[op][ti] = bv;
            }
#pragma unroll 2
            for (int c = 0; c < 64; ++c) {
                float4 zv4 = *(const float4*)(o1 + c * TT + tb);
                u64 zv[4] = {dup2f(zv4.x), dup2f(zv4.y), dup2f(zv4.z), dup2f(zv4.w)};
                ulonglong2 wa = *(const ulonglong2*)(w2 + c * 256 + ob2);
                ulonglong2 wb = *(const ulonglong2*)(w2 + c * 256 + ob2 + 4);
                u64 wp[4] = {wa.x, wa.y, wb.x, wb.y};
#pragma unroll
                for (int op = 0; op < 4; ++op)
#pragma unroll
                    for (int ti = 0; ti < 4; ++ti) fma2(acc[op][ti], wp[op], zv[ti]);
            }
#pragma unroll
            for (int op = 0; op < 4; ++op) {
                float lo[4], hi[4];
#pragma unroll
                for (int ti = 0; ti < 4; ++ti) upk(lo[ti], hi[ti], acc[op][ti]);
                float4 v0 = {lo[0], lo[1], lo[2], lo[3]};
                float4 v1 = {hi[0], hi[1], hi[2], hi[3]};
                *(float4*)&ob_out[(ob2 + 2 * op) * TLEN + t0 + tb] = v0;
                *(float4*)&ob_out[(ob2 + 2 * op + 1) * TLEN + t0 + tb] = v1;
            }
        }
    }
}

/* --------------------------------------------------------------- */
extern "C" void kernel_launch(void* const* d_in, const int* in_sizes, int n_in,
                              void* d_out, int out_size) {
    const float* x        = (const float*)d_in[0];
    const float* c        = (const float*)d_in[1];
    const float* first_w  = (const float*)d_in[2];
    const float* first_b  = (const float*)d_in[3];
    const float* conv_w   = (const float*)d_in[4];
    const float* conv_b   = (const float*)d_in[5];
    const float* cond_w   = (const float*)d_in[6];
    const float* out_w    = (const float*)d_in[7];
    const float* out_b    = (const float*)d_in[8];
    const float* skip_w   = (const float*)d_in[9];
    const float* skip_b   = (const float*)d_in[10];
    const float* last1_w  = (const float*)d_in[11];
    const float* last1_b  = (const float*)d_in[12];
    const float* last2_w  = (const float*)d_in[13];
    const float* last2_b  = (const float*)d_in[14];
    const float* conv_in_w= (const float*)d_in[15];
    const float* up_w0    = (const float*)d_in[16];
    const float* up_w1    = (const float*)d_in[17];
    float* out = (float*)d_out;

    int dev = 0;
    cudaGetDevice(&dev);
    int sms = 148;
    cudaDeviceGetAttribute(&sms, cudaDevAttrMultiProcessorCount, dev);

    cudaFuncSetAttribute(first_kernel, cudaFuncAttributeMaxDynamicSharedMemorySize, 131072);
    cudaFuncSetAttribute(layer_kernel, cudaFuncAttributeMaxDynamicSharedMemorySize, SM_TOTAL);
    cudaFuncSetAttribute(last_kernel,  cudaFuncAttributeMaxDynamicSharedMemorySize, 114688);

    {
        int total = NPG + NPZ + NPF;
        prep_all_kernel<<<(total + 255) / 256, 256>>>(
            conv_w, cond_w, skip_w, out_w, first_w, last1_w, last2_w);
    }
    cond_all_kernel<<<B_SZ * CCH, 256>>>(c, conv_in_w, up_w0, up_w1);
    first_kernel<<<sms, 256, 131072>>>(x, first_b);
    for (int l = 0; l < LAYERS; ++l) {
        int d = 1 << (l % 10);
        layer_kernel<<<sms, 256, SM_TOTAL>>>(l, d, l & 1, l == 0 ? 1 : 0,
                                             conv_b, skip_b, out_b);
    }
    last_kernel<<<sms, 256, 114688>>>(last1_b, last2_b, out);
}

// round 17
// speedup vs baseline: 1.2226x; 1.0231x over previous
#include <cuda_runtime.h>
#include <cuda_fp16.h>
#include <math.h>
#include <stdint.h>

#define LAYERS 30
#define B_SZ 4
#define TLEN 32000
#define TT 64
#define NTILES (B_SZ * (TLEN / TT))
#define LTT 64
#define LNT (B_SZ * (TLEN / LTT))   /* 2000 */
#define CH 64
#define CCH 80

/* layer SMEM: double B1, double B2, double epilogue staging */
#define STR 144
#define SM_BUF 59904
#define SM_B1M_OFF 29952
#define SM_B2 119808              /* + q*18432 ; mid at +9216 */
#define SM_EPI 156672             /* + e*35840 ; SK +0, HH +17408, HM +26624 */
#define EPI_STRIDE 35840
#define EPI_HH_OFF 17408
#define EPI_HM_OFF 26624
#define SM_TOTAL 228352

typedef unsigned long long u64;
typedef uint32_t u32;
typedef unsigned short u16;

__device__ __half g_hh[2][B_SZ * CH * TLEN];
__device__ __half g_hm[2][B_SZ * CH * TLEN];
__device__ float g_skips[B_SZ * CH * TLEN];
__device__ __half g_cbh[B_SZ * CCH * TLEN];
__device__ __half g_cbm[B_SZ * CCH * TLEN];
__device__ u32 g_gwh[LAYERS * 128 * 104];
__device__ u32 g_wzh[LAYERS * 128 * 32];
__device__ float g_wfirstT[256 * 64];
__device__ float g_wl1T[64 * 64];
__device__ float g_wl2T[64 * 256];

__device__ __forceinline__ u32 pkhf(float a, float b) {
    __half2 h = __floats2half2_rn(a, b);
    return *reinterpret_cast<u32*>(&h);
}
__device__ __forceinline__ float hflo(float a) { return __half2float(__float2half_rn(a)); }
__device__ __forceinline__ float2 uph2(u32 v) {
    __half2 h = *reinterpret_cast<__half2*>(&v);
    return make_float2(__half2float(h.x), __half2float(h.y));
}
__device__ __forceinline__ float gact(float a, float b) {
    a = fmaxf(a, -15.f);
    b = fmaxf(b, -30.f);
    float e1 = __expf(-2.f * a);
    float e2 = __expf(-b);
    return (1.f - e1) * __fdividef(1.f, (1.f + e1) * (1.f + e2));
}

__device__ __forceinline__ u32 smem_u32(const void* p) {
    u32 a;
    asm("{ .reg .u64 t; cvta.to.shared.u64 t, %1; cvt.u32.u64 %0, t; }" : "=r"(a) : "l"(p));
    return a;
}
__device__ __forceinline__ void mma16816(float* d, const u32* a, const u32* b) {
    asm volatile("mma.sync.aligned.m16n8k16.row.col.f32.f16.f16.f32 "
        "{%0,%1,%2,%3}, {%4,%5,%6,%7}, {%8,%9}, {%0,%1,%2,%3};"
        : "+f"(d[0]), "+f"(d[1]), "+f"(d[2]), "+f"(d[3])
        : "r"(a[0]), "r"(a[1]), "r"(a[2]), "r"(a[3]), "r"(b[0]), "r"(b[1]));
}
__device__ __forceinline__ void ldmT_x4(u32* r, u32 addr) {
    asm volatile("ldmatrix.sync.aligned.m8n8.x4.trans.shared.b16 {%0,%1,%2,%3}, [%4];"
        : "=r"(r[0]), "=r"(r[1]), "=r"(r[2]), "=r"(r[3]) : "r"(addr));
}
__device__ __forceinline__ void ldmT_x2(u32* r, u32 addr) {
    asm volatile("ldmatrix.sync.aligned.m8n8.x2.trans.shared.b16 {%0,%1}, [%2];"
        : "=r"(r[0]), "=r"(r[1]) : "r"(addr));
}
#define CP16(dst, src) asm volatile("cp.async.cg.shared.global [%0], [%1], 16;" \
    :: "r"((u32)(dst)), "l"(src) : "memory")
#define CP8(dst, src)  asm volatile("cp.async.ca.shared.global [%0], [%1], 8;" \
    :: "r"((u32)(dst)), "l"(src) : "memory")
#define CP4(dst, src)  asm volatile("cp.async.ca.shared.global [%0], [%1], 4;" \
    :: "r"((u32)(dst)), "l"(src) : "memory")
#define CP_COMMIT() asm volatile("cp.async.commit_group;" ::: "memory")
#define CP_WAIT0()  asm volatile("cp.async.wait_group 0;" ::: "memory")
#define STS32(a, v) asm volatile("st.shared.b32 [%0], %1;" :: "r"((u32)(a)), "r"((u32)(v)) : "memory")

__device__ __forceinline__ u64 pk2(float lo, float hi) {
    u64 r; asm("mov.b64 %0, {%1, %2};" : "=l"(r) : "f"(lo), "f"(hi)); return r;
}
__device__ __forceinline__ u64 dup2f(float v) { return pk2(v, v); }
__device__ __forceinline__ void fma2(u64& d, u64 a, u64 b) {
    asm("fma.rn.f32x2 %0, %1, %2, %0;" : "+l"(d) : "l"(a), "l"(b));
}
__device__ __forceinline__ void upk(float& lo, float& hi, u64 v) {
    asm("mov.b64 {%0, %1}, %2;" : "=f"(lo), "=f"(hi) : "l"(v));
}

__device__ __forceinline__ int orig_gate_row(int r) {
    int q = r >> 4, i = r & 15;
    return (i < 8) ? (8 * q + i) : (64 + 8 * q + (i - 8));
}

/* ---------------- merged weight prep ---------------- */
#define NPG (LAYERS * 128 * 104)
#define NPZ (LAYERS * 128 * 32)
#define NPF (16384 + 4096 + 16384)
__global__ void prep_all_kernel(const float* __restrict__ conv_w,
                                const float* __restrict__ cond_w,
                                const float* __restrict__ skip_w,
                                const float* __restrict__ out_w,
                                const float* __restrict__ first_w,
                                const float* __restrict__ last1_w,
                                const float* __restrict__ last2_w) {
    int idx = blockIdx.x * blockDim.x + threadIdx.x;
    if (idx < NPG) {
        int l = idx / (128 * 104), rem = idx % (128 * 104);
        int r = rem / 104, kp = rem % 104;
        int o = orig_gate_row(r);
        float w[2];
#pragma unroll
        for (int e = 0; e < 2; ++e) {
            int k = 2 * kp + e;
            if (k < 64)       w[e] = conv_w[((l * 128 + o) * 64 + k) * 2 + 0];
            else if (k < 128) w[e] = conv_w[((l * 128 + o) * 64 + (k - 64)) * 2 + 1];
            else              w[e] = cond_w[(l * 128 + o) * 80 + (k - 128)];
        }
        g_gwh[idx] = pkhf(w[0], w[1]);
    } else if (idx < NPG + NPZ) {
        int j = idx - NPG;
        int l = j / (128 * 32), rem = j % (128 * 32);
        int r = rem / 32, kp = rem % 32;
        float w[2];
#pragma unroll
        for (int e = 0; e < 2; ++e) {
            int k = 2 * kp + e;
            w[e] = (r < 64) ? skip_w[(l * 64 + r) * 64 + k]
                            : out_w[(l * 64 + (r - 64)) * 64 + k];
        }
        g_wzh[j] = pkhf(w[0], w[1]);
    } else if (idx < NPG + NPZ + NPF) {
        int j = idx - NPG - NPZ;
        if (j < 16384) {
            int c = j >> 6, o = j & 63;
            g_wfirstT[j] = first_w[o * 256 + c];
        } else if (j < 16384 + 4096) {
            int jj = j - 16384; int c = jj >> 6, o = jj & 63;
            g_wl1T[jj] = last1_w[o * 64 + c];
        } else {
            int jj = j - 16384 - 4096; int c = jj >> 8, o = jj & 255;
            g_wl2T[jj] = last2_w[o * 64 + c];
        }
    }
}

/* ---------------- merged conditioning ---------------- */
__global__ void __launch_bounds__(256) cond_all_kernel(
        const float* __restrict__ cin, const float* __restrict__ conv_in_w,
        const float* __restrict__ w0, const float* __restrict__ w1) {
    __shared__ float c1row[400];
    __shared__ float c2row[4000];
    int blk = blockIdx.x;
    int b = blk / CCH, o = blk % CCH;
    int tid = threadIdx.x;
    for (int f = tid; f < 400; f += 256) {
        const float* src = cin + (size_t)(b * CCH) * 400 + f;
        float acc = 0.f;
#pragma unroll 8
        for (int ch = 0; ch < 80; ++ch)
            acc += __ldg(&conv_in_w[o * 80 + ch]) * __ldg(&src[ch * 400]);
        c1row[f] = acc;
    }
    __syncthreads();
    for (int t = tid; t < 4000; t += 256) {
        float acc = 0.f;
        int base = t - 10;
        for (int j = 0; j < 21; ++j) {
            int u = base + j;
            if (u >= 0 && u < 4000) acc += __ldg(&w0[j]) * c1row[u / 10];
        }
        c2row[t] = acc;
    }
    __syncthreads();
    size_t rowoff = (size_t)(b * CCH + o) * TLEN;
    for (int t = tid; t < TLEN; t += 256) {
        float acc = 0.f;
        int base = t - 8;
        for (int j = 0; j < 17; ++j) {
            int u = base + j;
            if (u >= 0 && u < TLEN) acc += __ldg(&w1[j]) * c2row[u / 8];
        }
        g_cbh[rowoff + t] = __float2half_rn(acc);
        g_cbm[rowoff + t] = __float2half_rn(acc - hflo(acc));
    }
}

/* ---------------- first 1x1 conv (FFMA2) -> fp16 hi/mid planes ------------- */
__global__ void __launch_bounds__(256) first_kernel(const float* __restrict__ x,
                                                    const float* __restrict__ first_b) {
    extern __shared__ float sm[];
    float* xs = sm;
    float* wf = sm + 16384;
    for (int i = threadIdx.x; i < 16384 / 4; i += blockDim.x)
        ((float4*)wf)[i] = ((const float4*)g_wfirstT)[i];
    int to = threadIdx.x & 15, oo = threadIdx.x >> 4;
    int tb = to * 4, ob = oo * 4;
    for (int tile = blockIdx.x; tile < NTILES; tile += gridDim.x) {
        int b = tile / (TLEN / TT), t0 = (tile % (TLEN / TT)) * TT;
        __syncthreads();
        const float* xb = x + (size_t)b * 256 * TLEN;
        for (int i = threadIdx.x; i < 256 * (TT / 4); i += blockDim.x) {
            int c = i / (TT / 4), q = i % (TT / 4);
            ((float4*)xs)[c * (TT / 4) + q] = *(const float4*)&xb[c * TLEN + t0 + q * 4];
        }
        __syncthreads();
        u64 acc[2][4];
#pragma unroll
        for (int op = 0; op < 2; ++op) {
            u64 bv = pk2(first_b[ob + 2 * op], first_b[ob + 2 * op + 1]);
#pragma unroll
            for (int ti = 0; ti < 4; ++ti) acc[op][ti] = bv;
        }
#pragma unroll 2
        for (int c = 0; c < 256; ++c) {
            float4 xv4 = *(const float4*)(xs + c * TT + tb);
            u64 xv[4] = {dup2f(xv4.x), dup2f(xv4.y), dup2f(xv4.z), dup2f(xv4.w)};
            ulonglong2 wv = *(const ulonglong2*)(wf + c * 64 + ob);
            u64 w2[2] = {wv.x, wv.y};
#pragma unroll
            for (int op = 0; op < 2; ++op)
#pragma unroll
                for (int ti = 0; ti < 4; ++ti) fma2(acc[op][ti], w2[op], xv[ti]);
        }
        __half* hh = g_hh[0] + (size_t)b * CH * TLEN;
        __half* hm = g_hm[0] + (size_t)b * CH * TLEN;
#pragma unroll
        for (int op = 0; op < 2; ++op) {
            float lo[4], hi[4];
#pragma unroll
            for (int ti = 0; ti < 4; ++ti) upk(lo[ti], hi[ti], acc[op][ti]);
            int r0 = ob + 2 * op, r1 = r0 + 1;
            u32* p;
            p = (u32*)(hh + (size_t)r0 * TLEN + t0 + tb);
            p[0] = pkhf(lo[0], lo[1]); p[1] = pkhf(lo[2], lo[3]);
            p = (u32*)(hm + (size_t)r0 * TLEN + t0 + tb);
            p[0] = pkhf(lo[0] - hflo(lo[0]), lo[1] - hflo(lo[1]));
            p[1] = pkhf(lo[2] - hflo(lo[2]), lo[3] - hflo(lo[3]));
            p = (u32*)(hh + (size_t)r1 * TLEN + t0 + tb);
            p[0] = pkhf(hi[0], hi[1]); p[1] = pkhf(hi[2], hi[3]);
            p = (u32*)(hm + (size_t)r1 * TLEN + t0 + tb);
            p[0] = pkhf(hi[0] - hflo(hi[0]), hi[1] - hflo(hi[1]));
            p[1] = pkhf(hi[2] - hflo(hi[2]), hi[3] - hflo(hi[3]));
        }
    }
}

/* ---- async B1 issue ---- */
__device__ __forceinline__ void issue_b1(char* smc, u32 sb, u32 bufoff, int tile,
                                         int d, const __half* phh,
                                         const __half* phm, int tid) {
    int b = tile / (TLEN / LTT), t0 = (tile % (TLEN / LTT)) * LTT;
    const __half* hbh = phh + (size_t)b * CH * TLEN;
    const __half* hbm = phm + (size_t)b * CH * TLEN;
    u32 dsth = sb + bufoff;
    u32 dstm = dsth + SM_B1M_OFF;
    for (int i = tid; i < 144 * 8; i += 256) {
        int r = i >> 3, g = i & 7;
        const __half *s1, *s2;
        if (r < 64) {
            size_t a = (size_t)r * TLEN + t0 + g * 8;
            s1 = hbh + a; s2 = hbm + a;
        } else {
            size_t a = ((size_t)(b * CCH + r - 64)) * TLEN + t0 + g * 8;
            s1 = g_cbh + a; s2 = g_cbm + a;
        }
        u32 off = (u32)((64 + r) * STR + g * 16);
        CP16(dsth + off, s1);
        CP16(dstm + off, s2);
    }
    for (int i = tid; i < 64 * 8; i += 256) {
        int r = i >> 3, g = i & 7;
        int tg = t0 - d + g * 8;
        const __half* sh = hbh + (size_t)r * TLEN;
        const __half* sm2 = hbm + (size_t)r * TLEN;
        u32 off = (u32)(r * STR + g * 16);
        if (tg >= 0 && d >= 8) {
            CP16(dsth + off, sh + tg);
            CP16(dstm + off, sm2 + tg);
        } else if (tg >= 0 && d == 4) {
            CP8(dsth + off, sh + tg);      CP8(dsth + off + 8, sh + tg + 4);
            CP8(dstm + off, sm2 + tg);     CP8(dstm + off + 8, sm2 + tg + 4);
        } else if (tg >= 0 && d == 2) {
#pragma unroll
            for (int q = 0; q < 4; ++q) {
                CP4(dsth + off + q * 4, sh + tg + q * 2);
                CP4(dstm + off + q * 4, sm2 + tg + q * 2);
            }
        } else {
#pragma unroll
            for (int e = 0; e < 4; ++e) {
                int tt0 = tg + 2 * e, tt1 = tt0 + 1;
                u16 h0 = (tt0 >= 0) ? *(const u16*)(sh + tt0) : 0;
                u16 h1 = (tt1 >= 0) ? *(const u16*)(sh + tt1) : 0;
                u16 m0 = (tt0 >= 0) ? *(const u16*)(sm2 + tt0) : 0;
                u16 m1 = (tt1 >= 0) ? *(const u16*)(sm2 + tt1) : 0;
                STS32(dsth + off + e * 4, (u32)h0 | ((u32)h1 << 16));
                STS32(dstm + off + e * 4, (u32)m0 | ((u32)m1 << 16));
            }
        }
    }
}

/* ---- async epilogue staging into buffer eb ---- */
__device__ __forceinline__ void issue_epi(u32 sb, int eb, int tile,
                                          const __half* phh,
                                          const __half* phm, int tid) {
    int b = tile / (TLEN / LTT), t0 = (tile % (TLEN / LTT)) * LTT;
    const float* skb = g_skips + (size_t)b * CH * TLEN;
    const __half* hbh = phh + (size_t)b * CH * TLEN;
    const __half* hbm = phm + (size_t)b * CH * TLEN;
    u32 base = sb + SM_EPI + (u32)eb * EPI_STRIDE;
    for (int i = tid; i < 1024; i += 256) {
        int r = i >> 4, g = i & 15;
        CP16(base + r * 272 + g * 16, skb + (size_t)r * TLEN + t0 + g * 4);
    }
    for (int i = tid; i < 512; i += 256) {
        int r = i >> 3, g = i & 7;
        CP16(base + EPI_HH_OFF + r * 144 + g * 16, hbh + (size_t)r * TLEN + t0 + g * 8);
        CP16(base + EPI_HM_OFF + r * 144 + g * 16, hbm + (size_t)r * TLEN + t0 + g * 8);
    }
}

/* ---------------- fused residual layer: M=32/warp, j-split ----------------- */
__global__ void __launch_bounds__(256, 1) layer_kernel(int l, int d, int hin, int first_layer,
        const float* __restrict__ conv_b, const float* __restrict__ skip_b,
        const float* __restrict__ out_b) {
    extern __shared__ char smc[];
    u32 sb = smem_u32(smc);
    int tid = threadIdx.x, w = tid >> 5, lane = tid & 31;
    int lq = lane >> 2, lr = lane & 3;
    int wr = w & 3;          /* row group: gate rows 32*wr..32*wr+31 */
    int wj = w >> 2;         /* j group: j in [4*wj, 4*wj+4) */

    /* A fragments: 2 bands of 16 rows each */
    u32 Ah[2][13][4], Zh[2][4][4];
#pragma unroll
    for (int c = 0; c < 2; ++c) {
        const u32* gh = g_gwh + ((size_t)l * 128 + 32 * wr + 16 * c) * 104;
#pragma unroll
        for (int ks = 0; ks < 13; ++ks) {
            int kp = 8 * ks + lr;
            Ah[c][ks][0] = gh[lq * 104 + kp];     Ah[c][ks][1] = gh[(8 + lq) * 104 + kp];
            Ah[c][ks][2] = gh[lq * 104 + kp + 4]; Ah[c][ks][3] = gh[(8 + lq) * 104 + kp + 4];
        }
        const u32* zh = g_wzh + ((size_t)l * 128 + 32 * wr + 16 * c) * 32;
#pragma unroll
        for (int ks = 0; ks < 4; ++ks) {
            int kp = 8 * ks + lr;
            Zh[c][ks][0] = zh[lq * 32 + kp];     Zh[c][ks][1] = zh[(8 + lq) * 32 + kp];
            Zh[c][ks][2] = zh[lq * 32 + kp + 4]; Zh[c][ks][3] = zh[(8 + lq) * 32 + kp + 4];
        }
    }
    int gch[2];
    float ba[2], bb[2], bs0[2], bs1[2];
    int r1[2];
#pragma unroll
    for (int c = 0; c < 2; ++c) {
        int band = 2 * wr + c;
        gch[c] = 8 * band + lq;
        ba[c] = conv_b[l * 128 + gch[c]];
        bb[c] = conv_b[l * 128 + 64 + gch[c]];
        r1[c] = 16 * band + lq;
        bs0[c] = (r1[c] < 64) ? skip_b[l * 64 + r1[c]] : out_b[l * 64 + r1[c] - 64];
        bs1[c] = (r1[c] < 64) ? skip_b[l * 64 + r1[c] + 8] : out_b[l * 64 + r1[c] - 56];
    }

    const __half* phh = g_hh[hin];
    const __half* phm = g_hm[hin];
    __half* qhh = g_hh[hin ^ 1];
    __half* qhm = g_hm[hin ^ 1];

    int tile = blockIdx.x;
    if (tile >= LNT) return;

    issue_b1(smc, sb, 0, tile, d, phh, phm, tid);
    CP_COMMIT();
    CP_WAIT0();
    __syncthreads();

    int nt = tile + gridDim.x;
    if (nt < LNT)
        issue_b1(smc, sb, SM_BUF, nt, d, phh, phm, tid);
    issue_epi(sb, 0, tile, phh, phm, tid);
    CP_COMMIT();

    /* ---- macros for the two phases (band-doubled) ---- */
#define GATE_BODY(B1H4, B1M4, B1H2, B1M2, WB2H, WB2M)                            \
    for (int jj = 0; jj < 4; ++jj) {                                             \
        int j = 4 * wj + jj;                                                     \
        int ta = j * 16;                                                         \
        float D0[2][4] = {{0,0,0,0},{0,0,0,0}}, D1[2][4] = {{0,0,0,0},{0,0,0,0}};\
        _Pragma("unroll")                                                        \
        for (int kk = 0; kk < 6; ++kk) {                                         \
            u32 bh[4], bm[4];                                                    \
            ldmT_x4(bh, (B1H4) + kk * 32 * STR + ta);                            \
            ldmT_x4(bm, (B1M4) + kk * 32 * STR + ta);                            \
            _Pragma("unroll")                                                    \
            for (int c = 0; c < 2; ++c) {                                        \
                mma16816(D0[c], Ah[c][2 * kk], bh);                              \
                mma16816(D1[c], Ah[c][2 * kk], bm);                              \
                mma16816(D0[c], Ah[c][2 * kk + 1], bh + 2);                      \
                mma16816(D1[c], Ah[c][2 * kk + 1], bm + 2);                      \
            }                                                                    \
        }                                                                        \
        {                                                                        \
            u32 bh[2], bm[2];                                                    \
            ldmT_x2(bh, (B1H2) + ta);                                            \
            ldmT_x2(bm, (B1M2) + ta);                                            \
            _Pragma("unroll")                                                    \
            for (int c = 0; c < 2; ++c) {                                        \
                mma16816(D0[c], Ah[c][12], bh);                                  \
                mma16816(D1[c], Ah[c][12], bm);                                  \
            }                                                                    \
        }                                                                        \
        _Pragma("unroll")                                                        \
        for (int c = 0; c < 2; ++c) {                                            \
            float a0 = D0[c][0] + D1[c][0] + ba[c];                              \
            float a1 = D0[c][1] + D1[c][1] + ba[c];                              \
            float g0 = D0[c][2] + D1[c][2] + bb[c];                              \
            float g1 = D0[c][3] + D1[c][3] + bb[c];                              \
            float z0 = gact(a0, g0), z1 = gact(a1, g1);                          \
            int zoff = gch[c] * STR + (j * 8 + lr * 2) * 2;                      \
            *(u32*)(smc + (WB2H) + zoff) = pkhf(z0, z1);                         \
            *(u32*)(smc + (WB2M) + zoff) = pkhf(z0 - hflo(z0), z1 - hflo(z1));   \
        }                                                                        \
    }

#define SKIP_BODY(B2H4, B2M4, EPIB, B_S, T0_S)                                   \
    for (int jj = 0; jj < 4; ++jj) {                                             \
        int j = 4 * wj + jj;                                                     \
        int ta = j * 16;                                                         \
        float E0[2][4] = {{0,0,0,0},{0,0,0,0}}, E1[2][4] = {{0,0,0,0},{0,0,0,0}};\
        {                                                                        \
            u32 sh0[4], sm0[4], sh1[4], sm1[4];                                  \
            ldmT_x4(sh0, (B2H4) + ta);                                           \
            ldmT_x4(sm0, (B2M4) + ta);                                           \
            ldmT_x4(sh1, (B2H4) + 32 * STR + ta);                                \
            ldmT_x4(sm1, (B2M4) + 32 * STR + ta);                                \
            _Pragma("unroll")                                                    \
            for (int c = 0; c < 2; ++c) {                                        \
                mma16816(E0[c], Zh[c][0], sh0);                                  \
                mma16816(E1[c], Zh[c][0], sm0);                                  \
                mma16816(E0[c], Zh[c][1], sh0 + 2);                              \
                mma16816(E1[c], Zh[c][1], sm0 + 2);                              \
                mma16816(E0[c], Zh[c][2], sh1);                                  \
                mma16816(E1[c], Zh[c][2], sm1);                                  \
                mma16816(E0[c], Zh[c][3], sh1 + 2);                              \
                mma16816(E1[c], Zh[c][3], sm1 + 2);                              \
            }                                                                    \
        }                                                                        \
        int tl = j * 8 + lr * 2;                                                 \
        int t = (T0_S) + tl;                                                     \
        float* skb = g_skips + (size_t)(B_S) * CH * TLEN;                        \
        _Pragma("unroll")                                                        \
        for (int c = 0; c < 2; ++c) {                                            \
            float e0 = E0[c][0] + E1[c][0] + bs0[c];                             \
            float e1 = E0[c][1] + E1[c][1] + bs0[c];                             \
            float e2 = E0[c][2] + E1[c][2] + bs1[c];                             \
            float e3 = E0[c][3] + E1[c][3] + bs1[c];                             \
            if (r1[c] < 64) {                                                    \
                float2 v0 = {e0, e1}, v1 = {e2, e3};                             \
                if (!first_layer) {                                              \
                    float2 o0 = *(const float2*)((EPIB) + r1[c] * 272 + tl * 4); \
                    float2 o1 = *(const float2*)((EPIB) + (r1[c] + 8) * 272 + tl * 4); \
                    v0.x += o0.x; v0.y += o0.y; v1.x += o1.x; v1.y += o1.y;      \
                }                                                                \
                *(float2*)(skb + (size_t)r1[c] * TLEN + t) = v0;                 \
                *(float2*)(skb + (size_t)(r1[c] + 8) * TLEN + t) = v1;           \
            } else {                                                             \
                int c0 = r1[c] - 64, c1 = c0 + 8;                                \
                float2 i0h = uph2(*(const u32*)((EPIB) + EPI_HH_OFF + c0 * 144 + tl * 2)); \
                float2 i0m = uph2(*(const u32*)((EPIB) + EPI_HM_OFF + c0 * 144 + tl * 2)); \
                float2 i1h = uph2(*(const u32*)((EPIB) + EPI_HH_OFF + c1 * 144 + tl * 2)); \
                float2 i1m = uph2(*(const u32*)((EPIB) + EPI_HM_OFF + c1 * 144 + tl * 2)); \
                float v0 = e0 + i0h.x + i0m.x;                                   \
                float v1 = e1 + i0h.y + i0m.y;                                   \
                float v2 = e2 + i1h.x + i1m.x;                                   \
                float v3 = e3 + i1h.y + i1m.y;                                   \
                size_t a0i = (size_t)(B_S) * CH * TLEN + (size_t)c0 * TLEN + t;  \
                size_t a1i = (size_t)(B_S) * CH * TLEN + (size_t)c1 * TLEN + t;  \
                *(u32*)(qhh + a0i) = pkhf(v0, v1);                               \
                *(u32*)(qhm + a0i) = pkhf(v0 - hflo(v0), v1 - hflo(v1));         \
                *(u32*)(qhh + a1i) = pkhf(v2, v3);                               \
                *(u32*)(qhm + a1i) = pkhf(v2 - hflo(v2), v3 - hflo(v3));         \
            }                                                                    \
        }                                                                        \
    }

    /* peel: gate(T0) from buf0 -> B2[0] */
    {
        u32 bufH = sb;
        u32 bufM = bufH + SM_B1M_OFF;
        u32 b1h_l4 = bufH + lane * STR;
        u32 b1m_l4 = bufM + lane * STR;
        u32 b1h_l2 = bufH + (lane & 15) * STR + 192 * STR;
        u32 b1m_l2 = bufM + (lane & 15) * STR + 192 * STR;
        GATE_BODY(b1h_l4, b1m_l4, b1h_l2, b1m_l2, SM_B2, SM_B2 + 9216)
    }

    int gbuf = 1, zb = 0, eb = 0;

    while (nt < LNT) {
        CP_WAIT0();
        __syncthreads();

        int nnt = nt + gridDim.x;
        if (nnt < LNT)
            issue_b1(smc, sb, (u32)((gbuf ^ 1) * SM_BUF), nnt, d, phh, phm, tid);
        issue_epi(sb, eb ^ 1, nt, phh, phm, tid);
        CP_COMMIT();

        int b_s = tile / (TLEN / LTT), t0_s = (tile % (TLEN / LTT)) * LTT;
        u32 rb2h = sb + SM_B2 + zb * 18432;
        u32 rb2m = rb2h + 9216;
        u32 b2h_l4 = rb2h + lane * STR;
        u32 b2m_l4 = rb2m + lane * STR;
        int wb2h_off = SM_B2 + (zb ^ 1) * 18432;
        int wb2m_off = wb2h_off + 9216;
        u32 bufH = sb + gbuf * SM_BUF;
        u32 bufM = bufH + SM_B1M_OFF;
        u32 b1h_l4 = bufH + lane * STR;
        u32 b1m_l4 = bufM + lane * STR;
        u32 b1h_l2 = bufH + (lane & 15) * STR + 192 * STR;
        u32 b1m_l2 = bufM + (lane & 15) * STR + 192 * STR;
        const char* eB = smc + SM_EPI + (u32)eb * EPI_STRIDE;

        SKIP_BODY(b2h_l4, b2m_l4, eB, b_s, t0_s)
        GATE_BODY(b1h_l4, b1m_l4, b1h_l2, b1m_l2, wb2h_off, wb2m_off)

        tile = nt; nt = nnt; gbuf ^= 1; zb ^= 1; eb ^= 1;
    }

    /* final: skip(tile) */
    CP_WAIT0();
    __syncthreads();
    {
        int b_s = tile / (TLEN / LTT), t0_s = (tile % (TLEN / LTT)) * LTT;
        u32 rb2h = sb + SM_B2 + zb * 18432;
        u32 rb2m = rb2h + 9216;
        u32 b2h_l4 = rb2h + lane * STR;
        u32 b2m_l4 = rb2m + lane * STR;
        const char* eB = smc + SM_EPI + (u32)eb * EPI_STRIDE;
        SKIP_BODY(b2h_l4, b2m_l4, eB, b_s, t0_s)
    }
#undef GATE_BODY
#undef SKIP_BODY
}

/* ---------------- last: relu,1x1,relu,1x1 (FFMA2) ---------------- */
__global__ void __launch_bounds__(256) last_kernel(const float* __restrict__ l1b,
                                                   const float* __restrict__ l2b,
                                                   float* __restrict__ out) {
    extern __shared__ float sm[];
    float* w1 = sm;
    float* w2 = sm + 4096;
    float* sk = sm + 20480;
    float* o1 = sm + 24576;
    for (int i = threadIdx.x; i < 4096 / 4; i += blockDim.x)
        ((float4*)w1)[i] = ((const float4*)g_wl1T)[i];
    for (int i = threadIdx.x; i < 16384 / 4; i += blockDim.x)
        ((float4*)w2)[i] = ((const float4*)g_wl2T)[i];
    int to = threadIdx.x & 15, oo = threadIdx.x >> 4;
    int tb = to * 4;
    for (int tile = blockIdx.x; tile < NTILES; tile += gridDim.x) {
        int b = tile / (TLEN / TT), t0 = (tile % (TLEN / TT)) * TT;
        __syncthreads();
        const float* skb = g_skips + (size_t)b * CH * TLEN;
        for (int i = threadIdx.x; i < CH * (TT / 4); i += blockDim.x) {
            int c = i / (TT / 4), q = i % (TT / 4);
            float4 v = *(const float4*)&skb[c * TLEN + t0 + q * 4];
            v.x = fmaxf(v.x, 0.f); v.y = fmaxf(v.y, 0.f);
            v.z = fmaxf(v.z, 0.f); v.w = fmaxf(v.w, 0.f);
            ((float4*)sk)[c * (TT / 4) + q] = v;
        }
        __syncthreads();
        {
            int ob = oo * 4;
            u64 acc[2][4];
#pragma unroll
            for (int op = 0; op < 2; ++op) {
                u64 bv = pk2(l1b[ob + 2 * op], l1b[ob + 2 * op + 1]);
#pragma unroll
                for (int ti = 0; ti < 4; ++ti) acc[op][ti] = bv;
            }
#pragma unroll 2
            for (int c = 0; c < 64; ++c) {
                float4 xv4 = *(const float4*)(sk + c * TT + tb);
                u64 xv[4] = {dup2f(xv4.x), dup2f(xv4.y), dup2f(xv4.z), dup2f(xv4.w)};
                ulonglong2 wv = *(const ulonglong2*)(w1 + c * 64 + ob);
                u64 wp[2] = {wv.x, wv.y};
#pragma unroll
                for (int op = 0; op < 2; ++op)
#pragma unroll
                    for (int ti = 0; ti < 4; ++ti) fma2(acc[op][ti], wp[op], xv[ti]);
            }
#pragma unroll
            for (int op = 0; op < 2; ++op) {
                float lo[4], hi[4];
#pragma unroll
                for (int ti = 0; ti < 4; ++ti) upk(lo[ti], hi[ti], acc[op][ti]);
                float4 v0 = {fmaxf(lo[0], 0.f), fmaxf(lo[1], 0.f), fmaxf(lo[2], 0.f), fmaxf(lo[3], 0.f)};
                float4 v1 = {fmaxf(hi[0], 0.f), fmaxf(hi[1], 0.f), fmaxf(hi[2], 0.f), fmaxf(hi[3], 0.f)};
                *(float4*)(o1 + (ob + 2 * op) * TT + tb) = v0;
                *(float4*)(o1 + (ob + 2 * op + 1) * TT + tb) = v1;
            }
        }
        __syncthreads();
        float* ob_out = out + (size_t)b * 256 * TLEN;
#pragma unroll
        for (int half = 0; half < 2; ++half) {
            int ob2 = half * 128 + oo * 8;
            u64 acc[4][4];
#pragma unroll
            for (int op = 0; op < 4; ++op) {
                u64 bv = pk2(l2b[ob2 + 2 * op], l2b[ob2 + 2 * op + 1]);
#pragma unroll
                for (int ti = 0; ti < 4; ++ti) acc[op][ti] = bv;
            }
#pragma unroll 2
            for (int c = 0; c < 64; ++c) {
                float4 zv4 = *(const float4*)(o1 + c * TT + tb);
                u64 zv[4] = {dup2f(zv4.x), dup2f(zv4.y), dup2f(zv4.z), dup2f(zv4.w)};
                ulonglong2 wa = *(const ulonglong2*)(w2 + c * 256 + ob2);
                ulonglong2 wb = *(const ulonglong2*)(w2 + c * 256 + ob2 + 4);
                u64 wp[4] = {wa.x, wa.y, wb.x, wb.y};
#pragma unroll
                for (int op = 0; op < 4; ++op)
#pragma unroll
                    for (int ti = 0; ti < 4; ++ti) fma2(acc[op][ti], wp[op], zv[ti]);
            }
#pragma unroll
            for (int op = 0; op < 4; ++op) {
                float lo[4], hi[4];
#pragma unroll
                for (int ti = 0; ti < 4; ++ti) upk(lo[ti], hi[ti], acc[op][ti]);
                float4 v0 = {lo[0], lo[1], lo[2], lo[3]};
                float4 v1 = {hi[0], hi[1], hi[2], hi[3]};
                *(float4*)&ob_out[(ob2 + 2 * op) * TLEN + t0 + tb] = v0;
                *(float4*)&ob_out[(ob2 + 2 * op + 1) * TLEN + t0 + tb] = v1;
            }
        }
    }
}

/* --------------------------------------------------------------- */
extern "C" void kernel_launch(void* const* d_in, const int* in_sizes, int n_in,
                              void* d_out, int out_size) {
    const float* x        = (const float*)d_in[0];
    const float* c        = (const float*)d_in[1];
    const float* first_w  = (const float*)d_in[2];
    const float* first_b  = (const float*)d_in[3];
    const float* conv_w   = (const float*)d_in[4];
    const float* conv_b   = (const float*)d_in[5];
    const float* cond_w   = (const float*)d_in[6];
    const float* out_w    = (const float*)d_in[7];
    const float* out_b    = (const float*)d_in[8];
    const float* skip_w   = (const float*)d_in[9];
    const float* skip_b   = (const float*)d_in[10];
    const float* last1_w  = (const float*)d_in[11];
    const float* last1_b  = (const float*)d_in[12];
    const float* last2_w  = (const float*)d_in[13];
    const float* last2_b  = (const float*)d_in[14];
    const float* conv_in_w= (const float*)d_in[15];
    const float* up_w0    = (const float*)d_in[16];
    const float* up_w1    = (const float*)d_in[17];
    float* out = (float*)d_out;

    int dev = 0;
    cudaGetDevice(&dev);
    int sms = 148;
    cudaDeviceGetAttribute(&sms, cudaDevAttrMultiProcessorCount, dev);

    cudaFuncSetAttribute(first_kernel, cudaFuncAttributeMaxDynamicSharedMemorySize, 131072);
    cudaFuncSetAttribute(layer_kernel, cudaFuncAttributeMaxDynamicSharedMemorySize, SM_TOTAL);
    cudaFuncSetAttribute(last_kernel,  cudaFuncAttributeMaxDynamicSharedMemorySize, 114688);

    {
        int total = NPG + NPZ + NPF;
        prep_all_kernel<<<(total + 255) / 256, 256>>>(
            conv_w, cond_w, skip_w, out_w, first_w, last1_w, last2_w);
    }
    cond_all_kernel<<<B_SZ * CCH, 256>>>(c, conv_in_w, up_w0, up_w1);
    first_kernel<<<sms, 256, 131072>>>(x, first_b);
    for (int l = 0; l < LAYERS; ++l) {
        int d = 1 << (l % 10);
        layer_kernel<<<sms, 256, SM_TOTAL>>>(l, d, l & 1, l == 0 ? 1 : 0,
                                             conv_b, skip_b, out_b);
    }
    last_kernel<<<sms, 256, 114688>>>(last1_b, last2_b, out);
}